// round 5
// baseline (speedup 1.0000x reference)
#include <cuda_runtime.h>

#define BB  8
#define CC  256
#define NHD 8
#define HDD 32
#define SS  16384

// Scratch (allocation-free rule: __device__ globals)
__device__ float g_qp[BB * CC * SS];            // qp, then in-place softmaxed -> qs
__device__ float g_ctx[BB * NHD * HDD * HDD];   // sum_s exp(kp)*vp
__device__ float g_rsum[BB * NHD * HDD];        // sum_s exp(kp)
__device__ float g_M[BB * CC * CC];             // fused Wo*ctx/rowsum*scale

// ---------------------------------------------------------------- zero accums
__global__ void k_zero() {
    int i = blockIdx.x * 256 + threadIdx.x;
    if (i < BB * NHD * HDD * HDD) g_ctx[i] = 0.f;
    if (i < BB * NHD * HDD)       g_rsum[i] = 0.f;
}

// ------------------------------------------------- K1: projections + ctx epi
// CTA: (s-tile 128) x (head) x (batch). Computes 96x128 tile =
// [qp(32) ; kp(32) ; vp(32)] for one head. Writes qp; accumulates ctx/rowsum.
__global__ __launch_bounds__(256) void k_proj(
    const float* __restrict__ q,
    const float* __restrict__ wq, const float* __restrict__ bq,
    const float* __restrict__ wk, const float* __restrict__ bk,
    const float* __restrict__ wv, const float* __restrict__ bv)
{
    __shared__ __align__(16) float sbuf[8512];
    float* As = sbuf;          // [32][97]  (padded: avoid 32-way store conflicts)
    float* Bs = sbuf + 3104;   // [32][128]

    const int tid = threadIdx.x;
    const int tx = tid & 15, ty = tid >> 4;
    const int b = blockIdx.z, n = blockIdx.y;
    const int s0 = blockIdx.x * 128;

    float acc[6][8];
    #pragma unroll
    for (int r = 0; r < 6; r++) {
        int row = ty + 16 * r;
        int sec = row >> 5, hr = row & 31;
        const float* bias = (sec == 0) ? bq : (sec == 1) ? bk : bv;
        float b0 = bias[n * 32 + hr];
        #pragma unroll
        for (int c = 0; c < 8; c++) acc[r][c] = b0;
    }

    for (int k0 = 0; k0 < 256; k0 += 32) {
        // A: 96 rows (wq|wk|wv for head n) x 32 k, stored transposed
        for (int i = tid; i < 96 * 32; i += 256) {
            int row = i >> 5, kk = i & 31;
            int sec = row >> 5, hr = row & 31;
            const float* W = (sec == 0) ? wq : (sec == 1) ? wk : wv;
            As[kk * 97 + row] = W[(n * 32 + hr) * 256 + k0 + kk];
        }
        // B: q[b, k0..k0+31, s0..s0+127], float4 coalesced
        for (int i = tid; i < 32 * 32; i += 256) {
            int kk = i >> 5, c4 = i & 31;
            float4 v = *(const float4*)(q + (size_t)(b * 256 + k0 + kk) * SS + s0 + c4 * 4);
            *(float4*)(Bs + kk * 128 + c4 * 4) = v;
        }
        __syncthreads();
        #pragma unroll
        for (int kk = 0; kk < 32; kk++) {
            float a[6], bb[8];
            #pragma unroll
            for (int r = 0; r < 6; r++) a[r] = As[kk * 97 + ty + 16 * r];
            #pragma unroll
            for (int c = 0; c < 8; c++) bb[c] = Bs[kk * 128 + tx + 16 * c];
            #pragma unroll
            for (int r = 0; r < 6; r++)
                #pragma unroll
                for (int c = 0; c < 8; c++)
                    acc[r][c] += a[r] * bb[c];
        }
        __syncthreads();
    }

    // Epilogue: qp -> global; exp(kp), vp -> SMEM (reuse sbuf, pad 133)
    float* Ek = sbuf;          // [32][133]
    float* Vt = sbuf + 4256;   // [32][133]

    #pragma unroll
    for (int r = 0; r < 6; r++) {
        int row = ty + 16 * r;
        #pragma unroll
        for (int c = 0; c < 8; c++) {
            int col = tx + 16 * c;
            float v = acc[r][c];
            if (r < 2)      g_qp[(size_t)(b * 256 + n * 32 + row) * SS + s0 + col] = v;
            else if (r < 4) Ek[(row - 32) * 133 + col] = expf(v);
            else            Vt[(row - 64) * 133 + col] = v;
        }
    }
    __syncthreads();

    // rowsum(exp(kp)) partials: warp w handles rows 4w..4w+3
    {
        int w = tid >> 5, lane = tid & 31;
        #pragma unroll
        for (int rr = 0; rr < 4; rr++) {
            int i = w * 4 + rr;
            float s = 0.f;
            #pragma unroll
            for (int c = lane; c < 128; c += 32) s += Ek[i * 133 + c];
            #pragma unroll
            for (int off = 16; off > 0; off >>= 1)
                s += __shfl_xor_sync(0xffffffffu, s, off);
            if (lane == 0) atomicAdd(&g_rsum[(b * 8 + n) * 32 + i], s);
        }
    }
    // ctx partials: thread -> (i, j0..j0+3), dot over 128 spatials
    {
        int i = tid >> 3;
        int j0 = (tid & 7) * 4;
        float c0 = 0.f, c1 = 0.f, c2 = 0.f, c3 = 0.f;
        #pragma unroll 4
        for (int s = 0; s < 128; s++) {
            float e = Ek[i * 133 + s];
            c0 += e * Vt[(j0 + 0) * 133 + s];
            c1 += e * Vt[(j0 + 1) * 133 + s];
            c2 += e * Vt[(j0 + 2) * 133 + s];
            c3 += e * Vt[(j0 + 3) * 133 + s];
        }
        float* dst = &g_ctx[(((b * 8 + n) * 32) + i) * 32 + j0];
        atomicAdd(dst + 0, c0);
        atomicAdd(dst + 1, c1);
        atomicAdd(dst + 2, c2);
        atomicAdd(dst + 3, c3);
    }
}

// --------------------------------------- K2a: per-pixel softmax over d (in place)
__global__ __launch_bounds__(128) void k_qsoft() {
    int b = blockIdx.z, n = blockIdx.y;
    int s = blockIdx.x * 128 + threadIdx.x;
    size_t base = (size_t)(b * 256 + n * 32) * SS + s;
    float v[32];
    float sum = 0.f;
    #pragma unroll
    for (int i = 0; i < 32; i++) { v[i] = expf(g_qp[base + (size_t)i * SS]); sum += v[i]; }
    float inv = 1.f / sum;
    #pragma unroll
    for (int i = 0; i < 32; i++) g_qp[base + (size_t)i * SS] = v[i] * inv;
}

// ------------------- K2b: M_b[o, n*32+i] = scale * sum_j Wo[o,n*32+j]*ctx / rsum
__global__ __launch_bounds__(256) void k_M(const float* __restrict__ wo) {
    int o = blockIdx.x, b = blockIdx.y;
    int t = threadIdx.x;
    int n = t >> 5, i = t & 31;
    const float* ct = &g_ctx[((b * 8 + n) * 32 + i) * 32];
    const float* wr = &wo[o * 256 + n * 32];
    float s = 0.f;
    #pragma unroll
    for (int j = 0; j < 32; j++) s += wr[j] * ct[j];
    g_M[(b * 256 + o) * 256 + t] =
        s * 0.17677669529663687f / g_rsum[(b * 8 + n) * 32 + i];  // d^-0.5 = 32^-0.5
}

// ---------------------------- K3: final GEMM  out[b,o,s] = bo[o] + M_b @ qs
__global__ __launch_bounds__(256) void k_out(const float* __restrict__ bo,
                                             float* __restrict__ out)
{
    __shared__ __align__(16) float As[32 * 129];
    __shared__ __align__(16) float Bs[32 * 128];
    const int tid = threadIdx.x;
    const int tx = tid & 15, ty = tid >> 4;
    const int b = blockIdx.z;
    const int o0 = blockIdx.y * 128;
    const int s0 = blockIdx.x * 128;

    float acc[8][8];
    #pragma unroll
    for (int r = 0; r < 8; r++) {
        float b0 = bo[o0 + ty + 16 * r];
        #pragma unroll
        for (int c = 0; c < 8; c++) acc[r][c] = b0;
    }

    for (int k0 = 0; k0 < 256; k0 += 32) {
        for (int i = tid; i < 128 * 32; i += 256) {
            int row = i >> 5, kk = i & 31;
            As[kk * 129 + row] = g_M[(size_t)(b * 256 + o0 + row) * 256 + k0 + kk];
        }
        for (int i = tid; i < 32 * 32; i += 256) {
            int kk = i >> 5, c4 = i & 31;
            float4 v = *(const float4*)(g_qp + (size_t)(b * 256 + k0 + kk) * SS + s0 + c4 * 4);
            *(float4*)(Bs + kk * 128 + c4 * 4) = v;
        }
        __syncthreads();
        #pragma unroll
        for (int kk = 0; kk < 32; kk++) {
            float a[8], bb[8];
            #pragma unroll
            for (int r = 0; r < 8; r++) a[r] = As[kk * 129 + ty + 16 * r];
            #pragma unroll
            for (int c = 0; c < 8; c++) bb[c] = Bs[kk * 128 + tx + 16 * c];
            #pragma unroll
            for (int r = 0; r < 8; r++)
                #pragma unroll
                for (int c = 0; c < 8; c++)
                    acc[r][c] += a[r] * bb[c];
        }
        __syncthreads();
    }

    #pragma unroll
    for (int r = 0; r < 8; r++) {
        int o = o0 + ty + 16 * r;
        #pragma unroll
        for (int c = 0; c < 8; c++)
            out[(size_t)(b * 256 + o) * SS + s0 + tx + 16 * c] = acc[r][c];
    }
}

// ---------------------------------------------------------------------------
extern "C" void kernel_launch(void* const* d_in, const int* in_sizes, int n_in,
                              void* d_out, int out_size)
{
    const float* q  = (const float*)d_in[0];
    const float* wq = (const float*)d_in[1];
    const float* bq = (const float*)d_in[2];
    const float* wk = (const float*)d_in[3];
    const float* bk = (const float*)d_in[4];
    const float* wv = (const float*)d_in[5];
    const float* bv = (const float*)d_in[6];
    const float* wo = (const float*)d_in[7];
    const float* bo = (const float*)d_in[8];
    float* out = (float*)d_out;

    k_zero<<<256, 256>>>();
    k_proj<<<dim3(SS / 128, NHD, BB), 256>>>(q, wq, bq, wk, bk, wv, bv);
    k_qsoft<<<dim3(SS / 128, NHD, BB), 128>>>();
    k_M<<<dim3(CC, BB), 256>>>(wo);
    k_out<<<dim3(SS / 128, CC / 128, BB), 256>>>(bo, out);
}

// round 6
// speedup vs baseline: 1.0495x; 1.0495x over previous
#include <cuda_runtime.h>

#define BB  8
#define CC  256
#define NHD 8
#define HDD 32
#define SS  16384

// Scratch (allocation-free rule: __device__ globals)
__device__ float g_qp[BB * CC * SS];            // qp, then in-place softmaxed -> qs
__device__ float g_ctx[BB * NHD * HDD * HDD];   // sum_s exp(kp)*vp
__device__ float g_rsum[BB * NHD * HDD];        // sum_s exp(kp)
__device__ float g_M[BB * CC * CC];             // fused Wo*ctx/rowsum*scale

// ---------------------------------------------------------------- zero accums
__global__ void k_zero() {
    int i = blockIdx.x * 256 + threadIdx.x;
    if (i < BB * NHD * HDD * HDD) g_ctx[i] = 0.f;
    if (i < BB * NHD * HDD)       g_rsum[i] = 0.f;
}

// ------------------------------------------------- K1: projections + ctx epi
// CTA: (s-tile 128) x (head) x (batch). Computes 96x128 tile =
// [qp(32) ; kp(32) ; vp(32)] for one head. Writes qp; accumulates ctx/rowsum.
__global__ __launch_bounds__(256) void k_proj(
    const float* __restrict__ q,
    const float* __restrict__ wq, const float* __restrict__ bq,
    const float* __restrict__ wk, const float* __restrict__ bk,
    const float* __restrict__ wv, const float* __restrict__ bv)
{
    __shared__ __align__(16) float sbuf[8512];
    float* As = sbuf;          // [32][97]  (padded: avoid 32-way store conflicts)
    float* Bs = sbuf + 3104;   // [32][128]

    const int tid = threadIdx.x;
    const int tx = tid & 15, ty = tid >> 4;
    const int b = blockIdx.z, n = blockIdx.y;
    const int s0 = blockIdx.x * 128;

    float acc[6][8];
    #pragma unroll
    for (int r = 0; r < 6; r++) {
        int row = ty + 16 * r;
        int sec = row >> 5, hr = row & 31;
        const float* bias = (sec == 0) ? bq : (sec == 1) ? bk : bv;
        float b0 = bias[n * 32 + hr];
        #pragma unroll
        for (int c = 0; c < 8; c++) acc[r][c] = b0;
    }

    for (int k0 = 0; k0 < 256; k0 += 32) {
        // A: 96 rows (wq|wk|wv for head n) x 32 k, stored transposed
        for (int i = tid; i < 96 * 32; i += 256) {
            int row = i >> 5, kk = i & 31;
            int sec = row >> 5, hr = row & 31;
            const float* W = (sec == 0) ? wq : (sec == 1) ? wk : wv;
            As[kk * 97 + row] = W[(n * 32 + hr) * 256 + k0 + kk];
        }
        // B: q[b, k0..k0+31, s0..s0+127], float4 coalesced
        for (int i = tid; i < 32 * 32; i += 256) {
            int kk = i >> 5, c4 = i & 31;
            float4 v = *(const float4*)(q + (size_t)(b * 256 + k0 + kk) * SS + s0 + c4 * 4);
            *(float4*)(Bs + kk * 128 + c4 * 4) = v;
        }
        __syncthreads();
        #pragma unroll
        for (int kk = 0; kk < 32; kk++) {
            float a[6], bb[8];
            #pragma unroll
            for (int r = 0; r < 6; r++) a[r] = As[kk * 97 + ty + 16 * r];
            #pragma unroll
            for (int c = 0; c < 8; c++) bb[c] = Bs[kk * 128 + tx + 16 * c];
            #pragma unroll
            for (int r = 0; r < 6; r++)
                #pragma unroll
                for (int c = 0; c < 8; c++)
                    acc[r][c] += a[r] * bb[c];
        }
        __syncthreads();
    }

    // Epilogue: qp -> global; exp(kp), vp -> SMEM (reuse sbuf, pad 133)
    float* Ek = sbuf;          // [32][133]
    float* Vt = sbuf + 4256;   // [32][133]

    #pragma unroll
    for (int r = 0; r < 6; r++) {
        int row = ty + 16 * r;
        #pragma unroll
        for (int c = 0; c < 8; c++) {
            int col = tx + 16 * c;
            float v = acc[r][c];
            if (r < 2)      g_qp[(size_t)(b * 256 + n * 32 + row) * SS + s0 + col] = v;
            else if (r < 4) Ek[(row - 32) * 133 + col] = expf(v);
            else            Vt[(row - 64) * 133 + col] = v;
        }
    }
    __syncthreads();

    // rowsum(exp(kp)) partials: warp w handles rows 4w..4w+3
    {
        int w = tid >> 5, lane = tid & 31;
        #pragma unroll
        for (int rr = 0; rr < 4; rr++) {
            int i = w * 4 + rr;
            float s = 0.f;
            #pragma unroll
            for (int c = lane; c < 128; c += 32) s += Ek[i * 133 + c];
            #pragma unroll
            for (int off = 16; off > 0; off >>= 1)
                s += __shfl_xor_sync(0xffffffffu, s, off);
            if (lane == 0) atomicAdd(&g_rsum[(b * 8 + n) * 32 + i], s);
        }
    }
    // ctx partials: thread -> (i, j0..j0+3), dot over 128 spatials
    {
        int i = tid >> 3;
        int j0 = (tid & 7) * 4;
        float c0 = 0.f, c1 = 0.f, c2 = 0.f, c3 = 0.f;
        #pragma unroll 4
        for (int s = 0; s < 128; s++) {
            float e = Ek[i * 133 + s];
            c0 += e * Vt[(j0 + 0) * 133 + s];
            c1 += e * Vt[(j0 + 1) * 133 + s];
            c2 += e * Vt[(j0 + 2) * 133 + s];
            c3 += e * Vt[(j0 + 3) * 133 + s];
        }
        float* dst = &g_ctx[(((b * 8 + n) * 32) + i) * 32 + j0];
        atomicAdd(dst + 0, c0);
        atomicAdd(dst + 1, c1);
        atomicAdd(dst + 2, c2);
        atomicAdd(dst + 3, c3);
    }
}

// --------------------------------------- K2a: per-pixel softmax over d (in place)
__global__ __launch_bounds__(128) void k_qsoft() {
    int b = blockIdx.z, n = blockIdx.y;
    int s = blockIdx.x * 128 + threadIdx.x;
    size_t base = (size_t)(b * 256 + n * 32) * SS + s;
    float v[32];
    float sum = 0.f;
    #pragma unroll
    for (int i = 0; i < 32; i++) { v[i] = expf(g_qp[base + (size_t)i * SS]); sum += v[i]; }
    float inv = 1.f / sum;
    #pragma unroll
    for (int i = 0; i < 32; i++) g_qp[base + (size_t)i * SS] = v[i] * inv;
}

// ------------------- K2b: M_b[o, n*32+i] = scale * sum_j Wo[o,n*32+j]*ctx / rsum
__global__ __launch_bounds__(256) void k_M(const float* __restrict__ wo) {
    int o = blockIdx.x, b = blockIdx.y;
    int t = threadIdx.x;
    int n = t >> 5, i = t & 31;
    const float* ct = &g_ctx[((b * 8 + n) * 32 + i) * 32];
    const float* wr = &wo[o * 256 + n * 32];
    float s = 0.f;
    #pragma unroll
    for (int j = 0; j < 32; j++) s += wr[j] * ct[j];
    g_M[(b * 256 + o) * 256 + t] =
        s * 0.17677669529663687f / g_rsum[(b * 8 + n) * 32 + i];  // d^-0.5 = 32^-0.5
}

// ---------------------------- K3: final GEMM  out[b,o,s] = bo[o] + M_b @ qs
__global__ __launch_bounds__(256) void k_out(const float* __restrict__ bo,
                                             float* __restrict__ out)
{
    __shared__ __align__(16) float As[32 * 129];
    __shared__ __align__(16) float Bs[32 * 128];
    const int tid = threadIdx.x;
    const int tx = tid & 15, ty = tid >> 4;
    const int b = blockIdx.z;
    const int o0 = blockIdx.y * 128;
    const int s0 = blockIdx.x * 128;

    float acc[8][8];
    #pragma unroll
    for (int r = 0; r < 8; r++) {
        float b0 = bo[o0 + ty + 16 * r];
        #pragma unroll
        for (int c = 0; c < 8; c++) acc[r][c] = b0;
    }

    for (int k0 = 0; k0 < 256; k0 += 32) {
        for (int i = tid; i < 128 * 32; i += 256) {
            int row = i >> 5, kk = i & 31;
            As[kk * 129 + row] = g_M[(size_t)(b * 256 + o0 + row) * 256 + k0 + kk];
        }
        for (int i = tid; i < 32 * 32; i += 256) {
            int kk = i >> 5, c4 = i & 31;
            float4 v = *(const float4*)(g_qp + (size_t)(b * 256 + k0 + kk) * SS + s0 + c4 * 4);
            *(float4*)(Bs + kk * 128 + c4 * 4) = v;
        }
        __syncthreads();
        #pragma unroll
        for (int kk = 0; kk < 32; kk++) {
            float a[8], bb[8];
            #pragma unroll
            for (int r = 0; r < 8; r++) a[r] = As[kk * 129 + ty + 16 * r];
            #pragma unroll
            for (int c = 0; c < 8; c++) bb[c] = Bs[kk * 128 + tx + 16 * c];
            #pragma unroll
            for (int r = 0; r < 8; r++)
                #pragma unroll
                for (int c = 0; c < 8; c++)
                    acc[r][c] += a[r] * bb[c];
        }
        __syncthreads();
    }

    #pragma unroll
    for (int r = 0; r < 8; r++) {
        int o = o0 + ty + 16 * r;
        #pragma unroll
        for (int c = 0; c < 8; c++)
            out[(size_t)(b * 256 + o) * SS + s0 + tx + 16 * c] = acc[r][c];
    }
}

// ---------------------------------------------------------------------------
extern "C" void kernel_launch(void* const* d_in, const int* in_sizes, int n_in,
                              void* d_out, int out_size)
{
    const float* q  = (const float*)d_in[0];
    const float* wq = (const float*)d_in[1];
    const float* bq = (const float*)d_in[2];
    const float* wk = (const float*)d_in[3];
    const float* bk = (const float*)d_in[4];
    const float* wv = (const float*)d_in[5];
    const float* bv = (const float*)d_in[6];
    const float* wo = (const float*)d_in[7];
    const float* bo = (const float*)d_in[8];
    float* out = (float*)d_out;

    k_zero<<<256, 256>>>();
    k_proj<<<dim3(SS / 128, NHD, BB), 256>>>(q, wq, bq, wk, bk, wv, bv);
    k_qsoft<<<dim3(SS / 128, NHD, BB), 128>>>();
    k_M<<<dim3(CC, BB), 256>>>(wo);
    k_out<<<dim3(SS / 128, CC / 128, BB), 256>>>(bo, out);
}

// round 8
// speedup vs baseline: 2.3289x; 2.2190x over previous
#include <cuda_runtime.h>
#include <cuda_bf16.h>
#include <cstdint>

#define BB 8
#define SS 16384

// ------------------------------------------------------------- device scratch
__device__ __align__(16) __nv_bfloat16 g_qTh [BB * SS * 256];
__device__ __align__(16) __nv_bfloat16 g_qTl [BB * SS * 256];
__device__ __align__(16) __nv_bfloat16 g_qsTh[BB * SS * 256];
__device__ __align__(16) __nv_bfloat16 g_qsTl[BB * SS * 256];
__device__ __align__(16) __nv_bfloat16 g_W1h [768 * 256];
__device__ __align__(16) __nv_bfloat16 g_W1l [768 * 256];
__device__ float         g_bias1[768];
__device__ float         g_ctx [BB * 8 * 32 * 32];
__device__ float         g_rsum[BB * 256];
__device__ __align__(16) __nv_bfloat16 g_M3h [BB * 256 * 256];
__device__ __align__(16) __nv_bfloat16 g_M3l [BB * 256 * 256];

// ------------------------------------------------------------- smem layout
// GEMM: 2 stages x 4 tiles (Ah,Al,Bh,Bl), each 128 rows x 40 bf16 (stride pad)
#define TILE_B   10240               // 128*40*2
#define STAGE_B  40960               // 4 tiles
#define SMEM_DYN 81920               // 2 stages
// Epilogue (reuses same smem): S fp32 [128][132] + bias[128]
#define S_STRIDE 132
#define OFF_BIAS 67584               // bytes (= 128*132*4)

// ------------------------------------------------------------- PTX helpers
__device__ __forceinline__ uint32_t smem_u32(const void* p) {
    uint32_t a;
    asm("{ .reg .u64 t; cvta.to.shared.u64 t, %1; cvt.u32.u64 %0, t; }"
        : "=r"(a) : "l"(p));
    return a;
}
__device__ __forceinline__ void cpa16(uint32_t s, const void* g) {
    asm volatile("cp.async.cg.shared.global [%0], [%1], 16;" :: "r"(s), "l"(g));
}
__device__ __forceinline__ void cpa_commit() {
    asm volatile("cp.async.commit_group;" ::: "memory");
}
__device__ __forceinline__ void ldsm4(uint32_t* r, uint32_t addr) {
    asm volatile("ldmatrix.sync.aligned.m8n8.x4.shared.b16 {%0,%1,%2,%3}, [%4];"
                 : "=r"(r[0]), "=r"(r[1]), "=r"(r[2]), "=r"(r[3]) : "r"(addr));
}
__device__ __forceinline__ void mma16816(float* c, const uint32_t* a,
                                         const uint32_t* b) {
    asm volatile(
        "mma.sync.aligned.m16n8k16.row.col.f32.bf16.bf16.f32 "
        "{%0,%1,%2,%3}, {%4,%5,%6,%7}, {%8,%9}, {%0,%1,%2,%3};"
        : "+f"(c[0]), "+f"(c[1]), "+f"(c[2]), "+f"(c[3])
        : "r"(a[0]), "r"(a[1]), "r"(a[2]), "r"(a[3]), "r"(b[0]), "r"(b[1]));
}

// ------------------------------------------------------------- prep kernels
__global__ void k_prepw(const float* __restrict__ wq, const float* __restrict__ bq,
                        const float* __restrict__ wk, const float* __restrict__ bk,
                        const float* __restrict__ wv, const float* __restrict__ bv)
{
    int r = blockIdx.x, k = threadIdx.x;
    const float *W, *Bp; int src;
    if (r < 256) { W = wq; Bp = bq; src = r; }
    else {
        int q2 = r - 256, p = q2 >> 7, lr = q2 & 127;
        int sub = lr >> 5, ch = lr & 31, head = 2 * p + (sub >> 1);
        W = (sub & 1) ? wv : wk;  Bp = (sub & 1) ? bv : bk;
        src = head * 32 + ch;
    }
    float v = W[src * 256 + k];
    __nv_bfloat16 h = __float2bfloat16(v);
    g_W1h[r * 256 + k] = h;
    g_W1l[r * 256 + k] = __float2bfloat16(v - __bfloat162float(h));
    if (k == 0) g_bias1[r] = Bp[src];
}

// transpose q [b][c][s] -> qT [b][s][c], hi/lo bf16. 64c x 64s tiles.
__global__ __launch_bounds__(256) void k_prepq(const float* __restrict__ q)
{
    __shared__ float tile[64 * 68];
    int tid = threadIdx.x;
    int s0 = blockIdx.x * 64, c0 = blockIdx.y * 64, b = blockIdx.z;
    #pragma unroll
    for (int it = 0; it < 4; it++) {
        int i = tid + it * 256;
        int r = i >> 4, c4 = (i & 15) * 4;
        float4 v = *(const float4*)(q + (size_t)(b * 256 + c0 + r) * SS + s0 + c4);
        *(float4*)(tile + r * 68 + c4) = v;
    }
    __syncthreads();
    #pragma unroll
    for (int it = 0; it < 8; it++) {
        int u = tid + it * 256;
        int sl = u >> 5, cp = u & 31;
        float a = tile[(cp * 2 + 0) * 68 + sl];
        float c = tile[(cp * 2 + 1) * 68 + sl];
        __nv_bfloat16 ha = __float2bfloat16(a), hc = __float2bfloat16(c);
        __nv_bfloat162 hp = __halves2bfloat162(ha, hc);
        __nv_bfloat162 lp = __halves2bfloat162(
            __float2bfloat16(a - __bfloat162float(ha)),
            __float2bfloat16(c - __bfloat162float(hc)));
        size_t idx = ((size_t)(b * SS + s0 + sl) * 256 + c0) / 2 + cp;
        ((uint32_t*)g_qTh)[idx] = *(uint32_t*)&hp;
        ((uint32_t*)g_qTl)[idx] = *(uint32_t*)&lp;
    }
}

__global__ void k_zero() {
    int i = blockIdx.x * 256 + threadIdx.x;
    if (i < BB * 8 * 32 * 32) g_ctx[i] = 0.f;
    if (i < BB * 256)         g_rsum[i] = 0.f;
}

// ------------------------------------------------------------- GEMM mainloop
// 128x128x256 per CTA; warp (wm,wn) owns 64x32; acc[mi][ni][4] fp32.
__device__ __forceinline__ void load_chunk(
    uint32_t smb, int stage, int kc, int tid,
    const __nv_bfloat16* Ah, const __nv_bfloat16* Al,
    const __nv_bfloat16* Bh, const __nv_bfloat16* Bl)
{
    uint32_t sb = smb + stage * STAGE_B;
    #pragma unroll
    for (int it = 0; it < 2; it++) {
        int v = tid + it * 256;              // 0..511
        int row = v >> 2, q4 = v & 3;
        uint32_t so = row * 80 + q4 * 16;
        size_t go = (size_t)row * 256 + kc * 32 + q4 * 8;
        cpa16(sb + so,              Ah + go);
        cpa16(sb + TILE_B + so,     Al + go);
        cpa16(sb + 2 * TILE_B + so, Bh + go);
        cpa16(sb + 3 * TILE_B + so, Bl + go);
    }
}

__device__ __forceinline__ void gemm128(
    char* sm, float (&acc)[4][4][4],
    const __nv_bfloat16* Ah, const __nv_bfloat16* Al,
    const __nv_bfloat16* Bh, const __nv_bfloat16* Bl)
{
    const int tid = threadIdx.x, w = tid >> 5, l = tid & 31;
    const int wm = w >> 2, wn = w & 3;
    uint32_t smb = smem_u32(sm);

    #pragma unroll
    for (int mi = 0; mi < 4; mi++)
        #pragma unroll
        for (int ni = 0; ni < 4; ni++)
            #pragma unroll
            for (int r = 0; r < 4; r++) acc[mi][ni][r] = 0.f;

    // ldmatrix lane addressing (A row-major [m][k], B "col" = [n][k])
    uint32_t a_base = smb +
        ((wm * 64 + (l & 7) + ((l >> 3) & 1) * 8) * 40 + (l >> 4) * 8) * 2;
    uint32_t b_base = smb + 2 * TILE_B +
        ((wn * 32 + (l & 7) + (l >> 4) * 8) * 40 + ((l >> 3) & 1) * 8) * 2;

    load_chunk(smb, 0, 0, tid, Ah, Al, Bh, Bl);
    cpa_commit();

    for (int c = 0; c < 8; c++) {
        if (c < 7) {
            load_chunk(smb, (c + 1) & 1, c + 1, tid, Ah, Al, Bh, Bl);
            cpa_commit();
            asm volatile("cp.async.wait_group 1;" ::: "memory");
        } else {
            asm volatile("cp.async.wait_group 0;" ::: "memory");
        }
        __syncthreads();
        uint32_t st = (c & 1) * STAGE_B;
        #pragma unroll
        for (int ks = 0; ks < 2; ks++) {
            uint32_t bh[4][2], bl[4][2], t4[4];
            #pragma unroll
            for (int half = 0; half < 2; half++) {
                uint32_t ba = b_base + st + half * 1280 + ks * 32;
                ldsm4(t4, ba);
                bh[2*half][0] = t4[0]; bh[2*half][1] = t4[1];
                bh[2*half+1][0] = t4[2]; bh[2*half+1][1] = t4[3];
                ldsm4(t4, ba + TILE_B);
                bl[2*half][0] = t4[0]; bl[2*half][1] = t4[1];
                bl[2*half+1][0] = t4[2]; bl[2*half+1][1] = t4[3];
            }
            #pragma unroll
            for (int mi = 0; mi < 4; mi++) {
                uint32_t ah[4], al4[4];
                uint32_t aa = a_base + st + mi * 1280 + ks * 32;
                ldsm4(ah, aa);
                ldsm4(al4, aa + TILE_B);
                #pragma unroll
                for (int ni = 0; ni < 4; ni++) {
                    mma16816(acc[mi][ni], ah,  bh[ni]);
                    mma16816(acc[mi][ni], ah,  bl[ni]);
                    mma16816(acc[mi][ni], al4, bh[ni]);
                }
            }
        }
        __syncthreads();
    }
}

// store acc into S: transposed (S[spatial][channel]) if T, else natural.
template<bool T>
__device__ __forceinline__ void acc_to_smem(float* S, float (&acc)[4][4][4])
{
    const int tid = threadIdx.x, w = tid >> 5, l = tid & 31;
    const int wm = w >> 2, wn = w & 3;
    const int r0 = wm * 64 + (l >> 2), c0 = wn * 32 + (l & 3) * 2;
    #pragma unroll
    for (int mi = 0; mi < 4; mi++)
        #pragma unroll
        for (int ni = 0; ni < 4; ni++) {
            int r = r0 + mi * 16, cc = c0 + ni * 8;
            if (T) {
                S[cc * S_STRIDE + r]           = acc[mi][ni][0];
                S[(cc + 1) * S_STRIDE + r]     = acc[mi][ni][1];
                S[cc * S_STRIDE + r + 8]       = acc[mi][ni][2];
                S[(cc + 1) * S_STRIDE + r + 8] = acc[mi][ni][3];
            } else {
                S[r * S_STRIDE + cc]           = acc[mi][ni][0];
                S[r * S_STRIDE + cc + 1]       = acc[mi][ni][1];
                S[(r + 8) * S_STRIDE + cc]     = acc[mi][ni][2];
                S[(r + 8) * S_STRIDE + cc + 1] = acc[mi][ni][3];
            }
        }
}

// ------------------------------------------------------------- K1
__global__ void __launch_bounds__(256) k1()
{
    extern __shared__ char sm[];
    const int tid = threadIdx.x;
    const int b = blockIdx.z, y = blockIdx.y, s0 = blockIdx.x * 128;

    float acc[4][4][4];
    gemm128(sm, acc,
            g_W1h + y * 128 * 256, g_W1l + y * 128 * 256,
            g_qTh + ((size_t)b * SS + s0) * 256,
            g_qTl + ((size_t)b * SS + s0) * 256);

    float* S = (float*)sm;                       // [128 spatial][132 channel]
    float* sbias = (float*)(sm + OFF_BIAS);
    acc_to_smem<true>(S, acc);
    if (tid < 128) sbias[tid] = g_bias1[(y < 2 ? y : 2 + (y - 2)) * 128 +
                                        (y < 2 ? 0 : 0) + tid +
                                        (y >= 2 ? 128 * (y - 2) + 256 - 256 : 0)];
    // (simplify: channel bias for this row-block)
    if (tid < 128) sbias[tid] = g_bias1[y * 128 + tid];
    __syncthreads();

    if (y < 2) {
        // ---- q epilogue: softmax over d=32 per spatial, split hi/lo, write qsT
        const int sc = tid >> 1;
        #pragma unroll
        for (int g2 = 0; g2 < 2; g2++) {
            const int g = (tid & 1) * 2 + g2, gb = g * 32;
            float e[32], sum = 0.f;
            #pragma unroll
            for (int i = 0; i < 32; i++) {
                e[i] = __expf(S[sc * S_STRIDE + gb + i] + sbias[gb + i]);
                sum += e[i];
            }
            float inv = __fdividef(1.f, sum);
            __nv_bfloat16 oh[32], ol[32];
            #pragma unroll
            for (int i = 0; i < 32; i++) {
                float qv = e[i] * inv;
                __nv_bfloat16 h = __float2bfloat16(qv);
                oh[i] = h;
                ol[i] = __float2bfloat16(qv - __bfloat162float(h));
            }
            size_t go = ((size_t)b * SS + s0 + sc) * 256 + y * 128 + gb;
            #pragma unroll
            for (int v = 0; v < 4; v++) {
                *(uint4*)(g_qsTh + go + v * 8) = *(uint4*)(oh + v * 8);
                *(uint4*)(g_qsTl + go + v * 8) = *(uint4*)(ol + v * 8);
            }
        }
    } else {
        // ---- kv epilogue: in-place exp(k)+bias / v+bias, then ctx/rsum
        const int p = y - 2;
        {
            const int ch = tid & 127;
            const float bias = sbias[ch];
            const bool isk = ((ch >> 5) & 1) == 0;
            #pragma unroll 8
            for (int i = 0; i < 64; i++) {
                int sc = 2 * i + (tid >> 7);
                float v = S[sc * S_STRIDE + ch] + bias;
                S[sc * S_STRIDE + ch] = isk ? __expf(v) : v;
            }
        }
        __syncthreads();
        const int h = tid >> 7, i0 = ((tid >> 3) & 15) * 2, j0 = (tid & 7) * 4;
        float cacc[8] = {0,0,0,0,0,0,0,0};
        float r0 = 0.f, r1 = 0.f;
        const float* E = S + h * 64;
        const float* V = S + h * 64 + 32;
        #pragma unroll 4
        for (int sc = 0; sc < 128; sc++) {
            float e0 = E[sc * S_STRIDE + i0], e1 = E[sc * S_STRIDE + i0 + 1];
            r0 += e0; r1 += e1;
            float v0 = V[sc * S_STRIDE + j0 + 0], v1 = V[sc * S_STRIDE + j0 + 1];
            float v2 = V[sc * S_STRIDE + j0 + 2], v3 = V[sc * S_STRIDE + j0 + 3];
            cacc[0] += e0 * v0; cacc[1] += e0 * v1;
            cacc[2] += e0 * v2; cacc[3] += e0 * v3;
            cacc[4] += e1 * v0; cacc[5] += e1 * v1;
            cacc[6] += e1 * v2; cacc[7] += e1 * v3;
        }
        int gh = b * 8 + p * 2 + h;
        float* c0 = &g_ctx[(gh * 32 + i0) * 32 + j0];
        atomicAdd(c0 + 0, cacc[0]); atomicAdd(c0 + 1, cacc[1]);
        atomicAdd(c0 + 2, cacc[2]); atomicAdd(c0 + 3, cacc[3]);
        atomicAdd(c0 + 32, cacc[4]); atomicAdd(c0 + 33, cacc[5]);
        atomicAdd(c0 + 34, cacc[6]); atomicAdd(c0 + 35, cacc[7]);
        if (j0 == 0) {
            atomicAdd(&g_rsum[gh * 32 + i0], r0);
            atomicAdd(&g_rsum[gh * 32 + i0 + 1], r1);
        }
    }
}

// ------------------------------------------------------------- k_M3
__global__ __launch_bounds__(256) void k_M3(const float* __restrict__ wo)
{
    __shared__ float sctx[256 * 33];
    __shared__ float sw[256];
    __shared__ float sinv[256];
    int b = blockIdx.x, ot = blockIdx.y, tid = threadIdx.x;
    for (int idx = tid; idx < 8192; idx += 256) {
        int row = idx >> 5, j = idx & 31;
        sctx[row * 33 + j] = g_ctx[b * 8192 + idx];
    }
    sinv[tid] = 0.17677669529663687f / g_rsum[b * 256 + tid];
    __syncthreads();
    int n = tid >> 5;
    for (int oo = 0; oo < 32; oo++) {
        int o = ot * 32 + oo;
        __syncthreads();
        sw[tid] = wo[o * 256 + tid];
        __syncthreads();
        float s = 0.f;
        #pragma unroll
        for (int j = 0; j < 32; j++) s += sw[n * 32 + j] * sctx[tid * 33 + j];
        float m = s * sinv[tid];
        __nv_bfloat16 h = __float2bfloat16(m);
        g_M3h[(size_t)(b * 256 + o) * 256 + tid] = h;
        g_M3l[(size_t)(b * 256 + o) * 256 + tid] =
            __float2bfloat16(m - __bfloat162float(h));
    }
}

// ------------------------------------------------------------- K3
__global__ void __launch_bounds__(256) k3(const float* __restrict__ bo,
                                          float* __restrict__ outp)
{
    extern __shared__ char sm[];
    const int tid = threadIdx.x;
    const int b = blockIdx.z, y = blockIdx.y, s0 = blockIdx.x * 128;

    float acc[4][4][4];
    gemm128(sm, acc,
            g_M3h + (size_t)(b * 256 + y * 128) * 256,
            g_M3l + (size_t)(b * 256 + y * 128) * 256,
            g_qsTh + ((size_t)b * SS + s0) * 256,
            g_qsTl + ((size_t)b * SS + s0) * 256);

    float* S = (float*)sm;                       // [128 row][132 spatial]
    float* sbias = (float*)(sm + OFF_BIAS);
    acc_to_smem<false>(S, acc);
    if (tid < 128) sbias[tid] = bo[y * 128 + tid];
    __syncthreads();

    #pragma unroll 4
    for (int i2 = tid; i2 < 128 * 32; i2 += 256) {
        int rr = i2 >> 5, c4 = (i2 & 31) * 4;
        float4 v = *(float4*)(S + rr * S_STRIDE + c4);
        float bb2 = sbias[rr];
        v.x += bb2; v.y += bb2; v.z += bb2; v.w += bb2;
        *(float4*)(outp + (size_t)(b * 256 + y * 128 + rr) * SS + s0 + c4) = v;
    }
}

// ---------------------------------------------------------------------------
extern "C" void kernel_launch(void* const* d_in, const int* in_sizes, int n_in,
                              void* d_out, int out_size)
{
    const float* q  = (const float*)d_in[0];
    const float* wq = (const float*)d_in[1];
    const float* bq = (const float*)d_in[2];
    const float* wk = (const float*)d_in[3];
    const float* bk = (const float*)d_in[4];
    const float* wv = (const float*)d_in[5];
    const float* bv = (const float*)d_in[6];
    const float* wo = (const float*)d_in[7];
    const float* bo = (const float*)d_in[8];
    float* out = (float*)d_out;

    static int once = 0;
    if (!once) {
        cudaFuncSetAttribute(k1, cudaFuncAttributeMaxDynamicSharedMemorySize, SMEM_DYN);
        cudaFuncSetAttribute(k3, cudaFuncAttributeMaxDynamicSharedMemorySize, SMEM_DYN);
        once = 1;
    }

    k_zero<<<256, 256>>>();
    k_prepw<<<768, 256>>>(wq, bq, wk, bk, wv, bv);
    k_prepq<<<dim3(SS / 64, 4, BB), 256>>>(q);
    k1<<<dim3(SS / 128, 6, BB), 256, SMEM_DYN>>>();
    k_M3<<<dim3(BB, 8), 256>>>(wo);
    k3<<<dim3(SS / 128, 2, BB), 256, SMEM_DYN>>>(bo, out);
}

// round 10
// speedup vs baseline: 2.9140x; 1.2512x over previous
#include <cuda_runtime.h>
#include <cuda_bf16.h>
#include <cstdint>

#define BB 8
#define SS 16384

// ------------------------------------------------------------- device scratch
__device__ __align__(16) __nv_bfloat16 g_qTh [BB * SS * 256];
__device__ __align__(16) __nv_bfloat16 g_qTl [BB * SS * 256];
__device__ __align__(16) __nv_bfloat16 g_qsTh[BB * SS * 256];
__device__ __align__(16) __nv_bfloat16 g_qsTl[BB * SS * 256];
__device__ __align__(16) __nv_bfloat16 g_W1h [768 * 256];
__device__ __align__(16) __nv_bfloat16 g_W1l [768 * 256];
__device__ float         g_bias1[768];
__device__ float         g_ctx [BB * 8 * 32 * 32];
__device__ float         g_rsum[BB * 256];
__device__ __align__(16) __nv_bfloat16 g_M3h [BB * 256 * 256];
__device__ __align__(16) __nv_bfloat16 g_M3l [BB * 256 * 256];

// ------------------------------------------------------------- smem layout
// GEMM: 2 stages x 4 tiles (Ah,Al,Bh,Bl), each 128 rows x 40 bf16 (stride pad)
#define TILE_B   10240               // 128*40*2
#define STAGE_B  40960               // 4 tiles
#define SMEM_DYN 81920               // 2 stages
// Epilogue (reuses same smem): S fp32 [128][132] + bias[128]
#define S_STRIDE 132
#define OFF_BIAS 67584               // bytes (= 128*132*4)

// ------------------------------------------------------------- PTX helpers
__device__ __forceinline__ uint32_t smem_u32(const void* p) {
    uint32_t a;
    asm("{ .reg .u64 t; cvta.to.shared.u64 t, %1; cvt.u32.u64 %0, t; }"
        : "=r"(a) : "l"(p));
    return a;
}
__device__ __forceinline__ void cpa16(uint32_t s, const void* g) {
    asm volatile("cp.async.cg.shared.global [%0], [%1], 16;" :: "r"(s), "l"(g));
}
__device__ __forceinline__ void cpa_commit() {
    asm volatile("cp.async.commit_group;" ::: "memory");
}
__device__ __forceinline__ void ldsm4(uint32_t* r, uint32_t addr) {
    asm volatile("ldmatrix.sync.aligned.m8n8.x4.shared.b16 {%0,%1,%2,%3}, [%4];"
                 : "=r"(r[0]), "=r"(r[1]), "=r"(r[2]), "=r"(r[3]) : "r"(addr));
}
__device__ __forceinline__ void mma16816(float* c, const uint32_t* a,
                                         const uint32_t* b) {
    asm volatile(
        "mma.sync.aligned.m16n8k16.row.col.f32.bf16.bf16.f32 "
        "{%0,%1,%2,%3}, {%4,%5,%6,%7}, {%8,%9}, {%0,%1,%2,%3};"
        : "+f"(c[0]), "+f"(c[1]), "+f"(c[2]), "+f"(c[3])
        : "r"(a[0]), "r"(a[1]), "r"(a[2]), "r"(a[3]), "r"(b[0]), "r"(b[1]));
}

// ------------------------------------------------------------- prep kernels
__global__ void k_prepw(const float* __restrict__ wq, const float* __restrict__ bq,
                        const float* __restrict__ wk, const float* __restrict__ bk,
                        const float* __restrict__ wv, const float* __restrict__ bv)
{
    int r = blockIdx.x, k = threadIdx.x;
    const float *W, *Bp; int src;
    if (r < 256) { W = wq; Bp = bq; src = r; }
    else {
        int q2 = r - 256, p = q2 >> 7, lr = q2 & 127;
        int sub = lr >> 5, ch = lr & 31, head = 2 * p + (sub >> 1);
        W = (sub & 1) ? wv : wk;  Bp = (sub & 1) ? bv : bk;
        src = head * 32 + ch;
    }
    float v = W[src * 256 + k];
    __nv_bfloat16 h = __float2bfloat16(v);
    g_W1h[r * 256 + k] = h;
    g_W1l[r * 256 + k] = __float2bfloat16(v - __bfloat162float(h));
    if (k == 0) g_bias1[r] = Bp[src];
}

// transpose q [b][c][s] -> qT [b][s][c], hi/lo bf16. 64c x 64s tiles.
__global__ __launch_bounds__(256) void k_prepq(const float* __restrict__ q)
{
    __shared__ float tile[64 * 68];
    int tid = threadIdx.x;
    int s0 = blockIdx.x * 64, c0 = blockIdx.y * 64, b = blockIdx.z;
    #pragma unroll
    for (int it = 0; it < 4; it++) {
        int i = tid + it * 256;
        int r = i >> 4, c4 = (i & 15) * 4;
        float4 v = *(const float4*)(q + (size_t)(b * 256 + c0 + r) * SS + s0 + c4);
        *(float4*)(tile + r * 68 + c4) = v;
    }
    __syncthreads();
    #pragma unroll
    for (int it = 0; it < 8; it++) {
        int u = tid + it * 256;
        int sl = u >> 5, cp = u & 31;
        float a = tile[(cp * 2 + 0) * 68 + sl];
        float c = tile[(cp * 2 + 1) * 68 + sl];
        __nv_bfloat16 ha = __float2bfloat16(a), hc = __float2bfloat16(c);
        __nv_bfloat162 hp = __halves2bfloat162(ha, hc);
        __nv_bfloat162 lp = __halves2bfloat162(
            __float2bfloat16(a - __bfloat162float(ha)),
            __float2bfloat16(c - __bfloat162float(hc)));
        size_t idx = ((size_t)(b * SS + s0 + sl) * 256 + c0) / 2 + cp;
        ((uint32_t*)g_qTh)[idx] = *(uint32_t*)&hp;
        ((uint32_t*)g_qTl)[idx] = *(uint32_t*)&lp;
    }
}

__global__ void k_zero() {
    int i = blockIdx.x * 256 + threadIdx.x;
    if (i < BB * 8 * 32 * 32) g_ctx[i] = 0.f;
    if (i < BB * 256)         g_rsum[i] = 0.f;
}

// ------------------------------------------------------------- GEMM mainloop
// 128x128x256 per CTA; warp (wm,wn) owns 64x32; acc[mi][ni][4] fp32.
__device__ __forceinline__ void load_chunk(
    uint32_t smb, int stage, int kc, int tid,
    const __nv_bfloat16* Ah, const __nv_bfloat16* Al,
    const __nv_bfloat16* Bh, const __nv_bfloat16* Bl)
{
    uint32_t sb = smb + stage * STAGE_B;
    #pragma unroll
    for (int it = 0; it < 2; it++) {
        int v = tid + it * 256;              // 0..511
        int row = v >> 2, q4 = v & 3;
        uint32_t so = row * 80 + q4 * 16;
        size_t go = (size_t)row * 256 + kc * 32 + q4 * 8;
        cpa16(sb + so,              Ah + go);
        cpa16(sb + TILE_B + so,     Al + go);
        cpa16(sb + 2 * TILE_B + so, Bh + go);
        cpa16(sb + 3 * TILE_B + so, Bl + go);
    }
}

__device__ __forceinline__ void gemm128(
    char* sm, float (&acc)[4][4][4],
    const __nv_bfloat16* Ah, const __nv_bfloat16* Al,
    const __nv_bfloat16* Bh, const __nv_bfloat16* Bl)
{
    const int tid = threadIdx.x, w = tid >> 5, l = tid & 31;
    const int wm = w >> 2, wn = w & 3;
    uint32_t smb = smem_u32(sm);

    #pragma unroll
    for (int mi = 0; mi < 4; mi++)
        #pragma unroll
        for (int ni = 0; ni < 4; ni++)
            #pragma unroll
            for (int r = 0; r < 4; r++) acc[mi][ni][r] = 0.f;

    // ldmatrix lane addressing (A row-major [m][k], B "col" = [n][k])
    uint32_t a_base = smb +
        ((wm * 64 + (l & 7) + ((l >> 3) & 1) * 8) * 40 + (l >> 4) * 8) * 2;
    uint32_t b_base = smb + 2 * TILE_B +
        ((wn * 32 + (l & 7) + (l >> 4) * 8) * 40 + ((l >> 3) & 1) * 8) * 2;

    load_chunk(smb, 0, 0, tid, Ah, Al, Bh, Bl);
    cpa_commit();

    for (int c = 0; c < 8; c++) {
        if (c < 7) {
            load_chunk(smb, (c + 1) & 1, c + 1, tid, Ah, Al, Bh, Bl);
            cpa_commit();
            asm volatile("cp.async.wait_group 1;" ::: "memory");
        } else {
            asm volatile("cp.async.wait_group 0;" ::: "memory");
        }
        __syncthreads();
        uint32_t st = (c & 1) * STAGE_B;
        #pragma unroll
        for (int ks = 0; ks < 2; ks++) {
            uint32_t bh[4][2], bl[4][2], t4[4];
            #pragma unroll
            for (int half = 0; half < 2; half++) {
                uint32_t ba = b_base + st + half * 1280 + ks * 32;
                ldsm4(t4, ba);
                bh[2*half][0] = t4[0]; bh[2*half][1] = t4[1];
                bh[2*half+1][0] = t4[2]; bh[2*half+1][1] = t4[3];
                ldsm4(t4, ba + TILE_B);
                bl[2*half][0] = t4[0]; bl[2*half][1] = t4[1];
                bl[2*half+1][0] = t4[2]; bl[2*half+1][1] = t4[3];
            }
            #pragma unroll
            for (int mi = 0; mi < 4; mi++) {
                uint32_t ah[4], al4[4];
                uint32_t aa = a_base + st + mi * 1280 + ks * 32;
                ldsm4(ah, aa);
                ldsm4(al4, aa + TILE_B);
                #pragma unroll
                for (int ni = 0; ni < 4; ni++) {
                    mma16816(acc[mi][ni], ah,  bh[ni]);
                    mma16816(acc[mi][ni], ah,  bl[ni]);
                    mma16816(acc[mi][ni], al4, bh[ni]);
                }
            }
        }
        __syncthreads();
    }
}

// store acc into S: transposed (S[spatial][channel]) if T, else natural.
template<bool T>
__device__ __forceinline__ void acc_to_smem(float* S, float (&acc)[4][4][4])
{
    const int tid = threadIdx.x, w = tid >> 5, l = tid & 31;
    const int wm = w >> 2, wn = w & 3;
    const int r0 = wm * 64 + (l >> 2), c0 = wn * 32 + (l & 3) * 2;
    #pragma unroll
    for (int mi = 0; mi < 4; mi++)
        #pragma unroll
        for (int ni = 0; ni < 4; ni++) {
            int r = r0 + mi * 16, cc = c0 + ni * 8;
            if (T) {
                S[cc * S_STRIDE + r]           = acc[mi][ni][0];
                S[(cc + 1) * S_STRIDE + r]     = acc[mi][ni][1];
                S[cc * S_STRIDE + r + 8]       = acc[mi][ni][2];
                S[(cc + 1) * S_STRIDE + r + 8] = acc[mi][ni][3];
            } else {
                S[r * S_STRIDE + cc]           = acc[mi][ni][0];
                S[r * S_STRIDE + cc + 1]       = acc[mi][ni][1];
                S[(r + 8) * S_STRIDE + cc]     = acc[mi][ni][2];
                S[(r + 8) * S_STRIDE + cc + 1] = acc[mi][ni][3];
            }
        }
}

// ------------------------------------------------------------- K1
__global__ void __launch_bounds__(256, 2) k1()
{
    extern __shared__ char sm[];
    const int tid = threadIdx.x;
    const int b = blockIdx.z, y = blockIdx.y, s0 = blockIdx.x * 128;

    float acc[4][4][4];
    gemm128(sm, acc,
            g_W1h + y * 128 * 256, g_W1l + y * 128 * 256,
            g_qTh + ((size_t)b * SS + s0) * 256,
            g_qTl + ((size_t)b * SS + s0) * 256);

    float* S = (float*)sm;                       // [128 spatial][132 channel]
    float* sbias = (float*)(sm + OFF_BIAS);
    acc_to_smem<true>(S, acc);
    if (tid < 128) sbias[tid] = g_bias1[y * 128 + tid];
    __syncthreads();

    if (y < 2) {
        // ---- q epilogue: softmax over d=32 per spatial, split hi/lo, write qsT
        const int sc = tid >> 1;
        #pragma unroll
        for (int g2 = 0; g2 < 2; g2++) {
            const int g = (tid & 1) * 2 + g2, gb = g * 32;
            float e[32], sum = 0.f;
            #pragma unroll
            for (int i = 0; i < 32; i++) {
                e[i] = __expf(S[sc * S_STRIDE + gb + i] + sbias[gb + i]);
                sum += e[i];
            }
            float inv = __fdividef(1.f, sum);
            __nv_bfloat16 oh[32], ol[32];
            #pragma unroll
            for (int i = 0; i < 32; i++) {
                float qv = e[i] * inv;
                __nv_bfloat16 h = __float2bfloat16(qv);
                oh[i] = h;
                ol[i] = __float2bfloat16(qv - __bfloat162float(h));
            }
            size_t go = ((size_t)b * SS + s0 + sc) * 256 + y * 128 + gb;
            #pragma unroll
            for (int v = 0; v < 4; v++) {
                *(uint4*)(g_qsTh + go + v * 8) = *(uint4*)(oh + v * 8);
                *(uint4*)(g_qsTl + go + v * 8) = *(uint4*)(ol + v * 8);
            }
        }
    } else {
        // ---- kv epilogue: in-place exp(k)+bias / v+bias, then ctx/rsum
        const int p = y - 2;
        {
            const int ch = tid & 127;
            const float bias = sbias[ch];
            const bool isk = ((ch >> 5) & 1) == 0;
            #pragma unroll 8
            for (int i = 0; i < 64; i++) {
                int sc = 2 * i + (tid >> 7);
                float v = S[sc * S_STRIDE + ch] + bias;
                S[sc * S_STRIDE + ch] = isk ? __expf(v) : v;
            }
        }
        __syncthreads();
        const int h = tid >> 7, i0 = ((tid >> 3) & 15) * 2, j0 = (tid & 7) * 4;
        float cacc[8] = {0,0,0,0,0,0,0,0};
        float r0 = 0.f, r1 = 0.f;
        const float* E = S + h * 64;
        const float* V = S + h * 64 + 32;
        #pragma unroll 4
        for (int sc = 0; sc < 128; sc++) {
            float e0 = E[sc * S_STRIDE + i0], e1 = E[sc * S_STRIDE + i0 + 1];
            r0 += e0; r1 += e1;
            float v0 = V[sc * S_STRIDE + j0 + 0], v1 = V[sc * S_STRIDE + j0 + 1];
            float v2 = V[sc * S_STRIDE + j0 + 2], v3 = V[sc * S_STRIDE + j0 + 3];
            cacc[0] += e0 * v0; cacc[1] += e0 * v1;
            cacc[2] += e0 * v2; cacc[3] += e0 * v3;
            cacc[4] += e1 * v0; cacc[5] += e1 * v1;
            cacc[6] += e1 * v2; cacc[7] += e1 * v3;
        }
        int gh = b * 8 + p * 2 + h;
        float* c0 = &g_ctx[(gh * 32 + i0) * 32 + j0];
        atomicAdd(c0 + 0, cacc[0]); atomicAdd(c0 + 1, cacc[1]);
        atomicAdd(c0 + 2, cacc[2]); atomicAdd(c0 + 3, cacc[3]);
        atomicAdd(c0 + 32, cacc[4]); atomicAdd(c0 + 33, cacc[5]);
        atomicAdd(c0 + 34, cacc[6]); atomicAdd(c0 + 35, cacc[7]);
        if (j0 == 0) {
            atomicAdd(&g_rsum[gh * 32 + i0], r0);
            atomicAdd(&g_rsum[gh * 32 + i0 + 1], r1);
        }
    }
}

// ------------------------------------------------------------- k_M3
__global__ __launch_bounds__(256) void k_M3(const float* __restrict__ wo)
{
    __shared__ float sctx[256 * 33];
    __shared__ float sw[256];
    __shared__ float sinv[256];
    int b = blockIdx.x, ot = blockIdx.y, tid = threadIdx.x;
    for (int idx = tid; idx < 8192; idx += 256) {
        int row = idx >> 5, j = idx & 31;
        sctx[row * 33 + j] = g_ctx[b * 8192 + idx];
    }
    sinv[tid] = 0.17677669529663687f / g_rsum[b * 256 + tid];
    __syncthreads();
    int n = tid >> 5;
    for (int oo = 0; oo < 32; oo++) {
        int o = ot * 32 + oo;
        __syncthreads();
        sw[tid] = wo[o * 256 + tid];
        __syncthreads();
        float s = 0.f;
        #pragma unroll
        for (int j = 0; j < 32; j++) s += sw[n * 32 + j] * sctx[tid * 33 + j];
        float m = s * sinv[tid];
        __nv_bfloat16 h = __float2bfloat16(m);
        g_M3h[(size_t)(b * 256 + o) * 256 + tid] = h;
        g_M3l[(size_t)(b * 256 + o) * 256 + tid] =
            __float2bfloat16(m - __bfloat162float(h));
    }
}

// ------------------------------------------------------------- K3
__global__ void __launch_bounds__(256, 2) k3(const float* __restrict__ bo,
                                             float* __restrict__ outp)
{
    extern __shared__ char sm[];
    const int tid = threadIdx.x;
    const int b = blockIdx.z, y = blockIdx.y, s0 = blockIdx.x * 128;

    float acc[4][4][4];
    gemm128(sm, acc,
            g_M3h + (size_t)(b * 256 + y * 128) * 256,
            g_M3l + (size_t)(b * 256 + y * 128) * 256,
            g_qsTh + ((size_t)b * SS + s0) * 256,
            g_qsTl + ((size_t)b * SS + s0) * 256);

    float* S = (float*)sm;                       // [128 row][132 spatial]
    float* sbias = (float*)(sm + OFF_BIAS);
    acc_to_smem<false>(S, acc);
    if (tid < 128) sbias[tid] = bo[y * 128 + tid];
    __syncthreads();

    #pragma unroll 4
    for (int i2 = tid; i2 < 128 * 32; i2 += 256) {
        int rr = i2 >> 5, c4 = (i2 & 31) * 4;
        float4 v = *(float4*)(S + rr * S_STRIDE + c4);
        float bb2 = sbias[rr];
        v.x += bb2; v.y += bb2; v.z += bb2; v.w += bb2;
        *(float4*)(outp + (size_t)(b * 256 + y * 128 + rr) * SS + s0 + c4) = v;
    }
}

// ---------------------------------------------------------------------------
extern "C" void kernel_launch(void* const* d_in, const int* in_sizes, int n_in,
                              void* d_out, int out_size)
{
    const float* q  = (const float*)d_in[0];
    const float* wq = (const float*)d_in[1];
    const float* bq = (const float*)d_in[2];
    const float* wk = (const float*)d_in[3];
    const float* bk = (const float*)d_in[4];
    const float* wv = (const float*)d_in[5];
    const float* bv = (const float*)d_in[6];
    const float* wo = (const float*)d_in[7];
    const float* bo = (const float*)d_in[8];
    float* out = (float*)d_out;

    static int once = 0;
    if (!once) {
        cudaFuncSetAttribute(k1, cudaFuncAttributeMaxDynamicSharedMemorySize, SMEM_DYN);
        cudaFuncSetAttribute(k3, cudaFuncAttributeMaxDynamicSharedMemorySize, SMEM_DYN);
        once = 1;
    }

    k_zero<<<256, 256>>>();
    k_prepw<<<768, 256>>>(wq, bq, wk, bk, wv, bv);
    k_prepq<<<dim3(SS / 64, 4, BB), 256>>>(q);
    k1<<<dim3(SS / 128, 6, BB), 256, SMEM_DYN>>>();
    k_M3<<<dim3(BB, 8), 256>>>(wo);
    k3<<<dim3(SS / 128, 2, BB), 256, SMEM_DYN>>>(bo, out);
}

// round 11
// speedup vs baseline: 3.3438x; 1.1475x over previous
#include <cuda_runtime.h>
#include <cuda_bf16.h>
#include <cstdint>

#define BB 8
#define SS 16384

// ------------------------------------------------------------- device scratch
__device__ __align__(16) __nv_bfloat16 g_qTh [BB * SS * 256];
__device__ __align__(16) __nv_bfloat16 g_qTl [BB * SS * 256];
__device__ __align__(16) __nv_bfloat16 g_qsTh[BB * SS * 256];
__device__ __align__(16) __nv_bfloat16 g_qsTl[BB * SS * 256];
__device__ __align__(16) __nv_bfloat16 g_W1h [768 * 256];
__device__ __align__(16) __nv_bfloat16 g_W1l [768 * 256];
__device__ float         g_bias1[768];
__device__ float         g_ctx [BB * 8 * 32 * 32];
__device__ float         g_rsum[BB * 256];
__device__ __align__(16) __nv_bfloat16 g_M3h [BB * 256 * 256];
__device__ __align__(16) __nv_bfloat16 g_M3l [BB * 256 * 256];

// ------------------------------------------------------------- smem layout
// Stage = A-pair tile (128 rows x [hi 64B | lo 64B], SW128 swizzle) + B-pair.
#define PAIR_B   16384               // 128*128
#define STAGE_B  32768               // A-pair + B-pair
#define NSTAGE   3
#define SMEM_DYN 98304               // 3 stages (epilogue reuse fits: 68096)
// Epilogue (reuses same smem): S fp32 [128][132] + bias[128]
#define S_STRIDE 132
#define OFF_BIAS 67584               // bytes (= 128*132*4)

// ------------------------------------------------------------- PTX helpers
__device__ __forceinline__ uint32_t smem_u32(const void* p) {
    uint32_t a;
    asm("{ .reg .u64 t; cvta.to.shared.u64 t, %1; cvt.u32.u64 %0, t; }"
        : "=r"(a) : "l"(p));
    return a;
}
__device__ __forceinline__ void cpa16(uint32_t s, const void* g) {
    asm volatile("cp.async.cg.shared.global [%0], [%1], 16;" :: "r"(s), "l"(g));
}
__device__ __forceinline__ void cpa_commit() {
    asm volatile("cp.async.commit_group;" ::: "memory");
}
__device__ __forceinline__ void ldsm4(uint32_t* r, uint32_t addr) {
    asm volatile("ldmatrix.sync.aligned.m8n8.x4.shared.b16 {%0,%1,%2,%3}, [%4];"
                 : "=r"(r[0]), "=r"(r[1]), "=r"(r[2]), "=r"(r[3]) : "r"(addr));
}
__device__ __forceinline__ void mma16816(float* c, const uint32_t* a,
                                         const uint32_t* b) {
    asm volatile(
        "mma.sync.aligned.m16n8k16.row.col.f32.bf16.bf16.f32 "
        "{%0,%1,%2,%3}, {%4,%5,%6,%7}, {%8,%9}, {%0,%1,%2,%3};"
        : "+f"(c[0]), "+f"(c[1]), "+f"(c[2]), "+f"(c[3])
        : "r"(a[0]), "r"(a[1]), "r"(a[2]), "r"(a[3]), "r"(b[0]), "r"(b[1]));
}

// ------------------------------------------------------------- prep kernels
// Also zeroes ctx/rsum accumulators (folded launch).
__global__ void k_prepw(const float* __restrict__ wq, const float* __restrict__ bq,
                        const float* __restrict__ wk, const float* __restrict__ bk,
                        const float* __restrict__ wv, const float* __restrict__ bv)
{
    int r = blockIdx.x, k = threadIdx.x;
    int z = r * 256 + k;
    if (z < BB * 8 * 32 * 32) g_ctx[z] = 0.f;
    if (z < BB * 256)         g_rsum[z] = 0.f;

    const float *W, *Bp; int src;
    if (r < 256) { W = wq; Bp = bq; src = r; }
    else {
        int q2 = r - 256, p = q2 >> 7, lr = q2 & 127;
        int sub = lr >> 5, ch = lr & 31, head = 2 * p + (sub >> 1);
        W = (sub & 1) ? wv : wk;  Bp = (sub & 1) ? bv : bk;
        src = head * 32 + ch;
    }
    float v = W[src * 256 + k];
    __nv_bfloat16 h = __float2bfloat16(v);
    g_W1h[r * 256 + k] = h;
    g_W1l[r * 256 + k] = __float2bfloat16(v - __bfloat162float(h));
    if (k == 0) g_bias1[r] = Bp[src];
}

// transpose q [b][c][s] -> qT [b][s][c], hi/lo bf16. 64c x 64s tiles.
__global__ __launch_bounds__(256) void k_prepq(const float* __restrict__ q)
{
    __shared__ float tile[64 * 68];
    int tid = threadIdx.x;
    int s0 = blockIdx.x * 64, c0 = blockIdx.y * 64, b = blockIdx.z;
    #pragma unroll
    for (int it = 0; it < 4; it++) {
        int i = tid + it * 256;
        int r = i >> 4, c4 = (i & 15) * 4;
        float4 v = *(const float4*)(q + (size_t)(b * 256 + c0 + r) * SS + s0 + c4);
        *(float4*)(tile + r * 68 + c4) = v;
    }
    __syncthreads();
    #pragma unroll
    for (int it = 0; it < 8; it++) {
        int u = tid + it * 256;
        int sl = u >> 5, cp = u & 31;
        float a = tile[(cp * 2 + 0) * 68 + sl];
        float c = tile[(cp * 2 + 1) * 68 + sl];
        __nv_bfloat16 ha = __float2bfloat16(a), hc = __float2bfloat16(c);
        __nv_bfloat162 hp = __halves2bfloat162(ha, hc);
        __nv_bfloat162 lp = __halves2bfloat162(
            __float2bfloat16(a - __bfloat162float(ha)),
            __float2bfloat16(c - __bfloat162float(hc)));
        size_t idx = ((size_t)(b * SS + s0 + sl) * 256 + c0) / 2 + cp;
        ((uint32_t*)g_qTh)[idx] = *(uint32_t*)&hp;
        ((uint32_t*)g_qTl)[idx] = *(uint32_t*)&lp;
    }
}

// ------------------------------------------------------------- GEMM mainloop
// 128x128x256 per CTA; warp (wm,wn) owns 64x32; acc[mi][ni][4] fp32.
// Stage layout: A-pair rows: [Ah(k 0..31) | Al(k 0..31)], SW128-swizzled.
__device__ __forceinline__ void load_chunk(
    uint32_t sb, int kc, int tid,
    const __nv_bfloat16* Ah, const __nv_bfloat16* Al,
    const __nv_bfloat16* Bh, const __nv_bfloat16* Bl)
{
    const int c16 = tid & 7;
    const __nv_bfloat16* srcA = (c16 < 4 ? Ah : Al);
    const __nv_bfloat16* srcB = (c16 < 4 ? Bh : Bl);
    const int kb = kc * 32 + (c16 & 3) * 8;
    #pragma unroll
    for (int it = 0; it < 4; it++) {
        int row = (tid >> 3) + it * 32;
        uint32_t so = row * 128 + ((c16 ^ (row & 7)) << 4);
        cpa16(sb + so,          srcA + (size_t)row * 256 + kb);
        cpa16(sb + PAIR_B + so, srcB + (size_t)row * 256 + kb);
    }
}

__device__ __forceinline__ void gemm128(
    char* sm, float (&acc)[4][4][4],
    const __nv_bfloat16* Ah, const __nv_bfloat16* Al,
    const __nv_bfloat16* Bh, const __nv_bfloat16* Bl)
{
    const int tid = threadIdx.x, w = tid >> 5, l = tid & 31;
    const int wm = w >> 2, wn = w & 3;
    uint32_t smb = smem_u32(sm);

    #pragma unroll
    for (int mi = 0; mi < 4; mi++)
        #pragma unroll
        for (int ni = 0; ni < 4; ni++)
            #pragma unroll
            for (int r = 0; r < 4; r++) acc[mi][ni][r] = 0.f;

    // per-lane ldmatrix row bases (row&7 invariant under +16-row steps)
    const int arow = wm * 64 + (l & 7) + ((l >> 3) & 1) * 8;
    const uint32_t a_off = (uint32_t)arow * 128;
    const int arsw = arow & 7, la = l >> 4;
    const int brow = wn * 32 + (l & 7) + (l >> 4) * 8;
    const uint32_t b_off = PAIR_B + (uint32_t)brow * 128;
    const int brsw = brow & 7, lb = (l >> 3) & 1;

    load_chunk(smb, 0, tid, Ah, Al, Bh, Bl);
    cpa_commit();

    uint32_t st = smb, ld = smb + STAGE_B;
    #pragma unroll 1
    for (int c = 0; c < 8; c++) {
        if (c < 7) {
            load_chunk(ld, c + 1, tid, Ah, Al, Bh, Bl);
            cpa_commit();
            ld += STAGE_B; if (ld == smb + NSTAGE * STAGE_B) ld = smb;
            asm volatile("cp.async.wait_group 1;" ::: "memory");
        } else {
            asm volatile("cp.async.wait_group 0;" ::: "memory");
        }
        __syncthreads();
        #pragma unroll
        for (int ks = 0; ks < 2; ks++) {
            uint32_t bh[4][2], bl4[4][2], t4[4];
            #pragma unroll
            for (int half = 0; half < 2; half++) {
                uint32_t ba = st + b_off + half * 2048 +
                              (((ks * 2 + lb) ^ brsw) << 4);
                ldsm4(t4, ba);
                bh[2*half][0] = t4[0]; bh[2*half][1] = t4[1];
                bh[2*half+1][0] = t4[2]; bh[2*half+1][1] = t4[3];
                ldsm4(t4, ba ^ 64);
                bl4[2*half][0] = t4[0]; bl4[2*half][1] = t4[1];
                bl4[2*half+1][0] = t4[2]; bl4[2*half+1][1] = t4[3];
            }
            #pragma unroll
            for (int mi = 0; mi < 4; mi++) {
                uint32_t ah[4], al4[4];
                uint32_t aa = st + a_off + mi * 2048 +
                              (((ks * 2 + la) ^ arsw) << 4);
                ldsm4(ah, aa);
                ldsm4(al4, aa ^ 64);
                #pragma unroll
                for (int ni = 0; ni < 4; ni++) {
                    mma16816(acc[mi][ni], ah,  bh[ni]);
                    mma16816(acc[mi][ni], ah,  bl4[ni]);
                    mma16816(acc[mi][ni], al4, bh[ni]);
                }
            }
        }
        st += STAGE_B; if (st == smb + NSTAGE * STAGE_B) st = smb;
    }
    __syncthreads();   // protect stage smem before epilogue reuse
}

// store acc into S: transposed (S[spatial][channel]) if T, else natural.
template<bool T>
__device__ __forceinline__ void acc_to_smem(float* S, float (&acc)[4][4][4])
{
    const int tid = threadIdx.x, w = tid >> 5, l = tid & 31;
    const int wm = w >> 2, wn = w & 3;
    const int r0 = wm * 64 + (l >> 2), c0 = wn * 32 + (l & 3) * 2;
    #pragma unroll
    for (int mi = 0; mi < 4; mi++)
        #pragma unroll
        for (int ni = 0; ni < 4; ni++) {
            int r = r0 + mi * 16, cc = c0 + ni * 8;
            if (T) {
                S[cc * S_STRIDE + r]           = acc[mi][ni][0];
                S[(cc + 1) * S_STRIDE + r]     = acc[mi][ni][1];
                S[cc * S_STRIDE + r + 8]       = acc[mi][ni][2];
                S[(cc + 1) * S_STRIDE + r + 8] = acc[mi][ni][3];
            } else {
                S[r * S_STRIDE + cc]           = acc[mi][ni][0];
                S[r * S_STRIDE + cc + 1]       = acc[mi][ni][1];
                S[(r + 8) * S_STRIDE + cc]     = acc[mi][ni][2];
                S[(r + 8) * S_STRIDE + cc + 1] = acc[mi][ni][3];
            }
        }
}

// ------------------------------------------------------------- K1
__global__ void __launch_bounds__(256, 2) k1()
{
    extern __shared__ char sm[];
    const int tid = threadIdx.x;
    const int b = blockIdx.z, y = blockIdx.y, s0 = blockIdx.x * 128;

    float acc[4][4][4];
    gemm128(sm, acc,
            g_W1h + y * 128 * 256, g_W1l + y * 128 * 256,
            g_qTh + ((size_t)b * SS + s0) * 256,
            g_qTl + ((size_t)b * SS + s0) * 256);

    float* S = (float*)sm;                       // [128 spatial][132 channel]
    float* sbias = (float*)(sm + OFF_BIAS);
    acc_to_smem<true>(S, acc);
    if (tid < 128) sbias[tid] = g_bias1[y * 128 + tid];
    __syncthreads();

    if (y < 2) {
        // ---- q epilogue: softmax over d=32 per spatial, split hi/lo, write qsT
        const int sc = tid >> 1;
        #pragma unroll
        for (int g2 = 0; g2 < 2; g2++) {
            const int g = (tid & 1) * 2 + g2, gb = g * 32;
            float e[32], sum = 0.f;
            #pragma unroll
            for (int i = 0; i < 32; i++) {
                e[i] = __expf(S[sc * S_STRIDE + gb + i] + sbias[gb + i]);
                sum += e[i];
            }
            float inv = __fdividef(1.f, sum);
            __nv_bfloat16 oh[32], ol[32];
            #pragma unroll
            for (int i = 0; i < 32; i++) {
                float qv = e[i] * inv;
                __nv_bfloat16 h = __float2bfloat16(qv);
                oh[i] = h;
                ol[i] = __float2bfloat16(qv - __bfloat162float(h));
            }
            size_t go = ((size_t)b * SS + s0 + sc) * 256 + y * 128 + gb;
            #pragma unroll
            for (int v = 0; v < 4; v++) {
                *(uint4*)(g_qsTh + go + v * 8) = *(uint4*)(oh + v * 8);
                *(uint4*)(g_qsTl + go + v * 8) = *(uint4*)(ol + v * 8);
            }
        }
    } else {
        // ---- kv epilogue: in-place exp(k)+bias / v+bias, then ctx/rsum
        const int p = y - 2;
        {
            const int ch = tid & 127;
            const float bias = sbias[ch];
            const bool isk = ((ch >> 5) & 1) == 0;
            #pragma unroll 8
            for (int i = 0; i < 64; i++) {
                int sc = 2 * i + (tid >> 7);
                float v = S[sc * S_STRIDE + ch] + bias;
                S[sc * S_STRIDE + ch] = isk ? __expf(v) : v;
            }
        }
        __syncthreads();
        const int h = tid >> 7, i0 = ((tid >> 3) & 15) * 2, j0 = (tid & 7) * 4;
        float cacc[8] = {0,0,0,0,0,0,0,0};
        float r0 = 0.f, r1 = 0.f;
        const float* E = S + h * 64;
        const float* V = S + h * 64 + 32;
        #pragma unroll 4
        for (int sc = 0; sc < 128; sc++) {
            float e0 = E[sc * S_STRIDE + i0], e1 = E[sc * S_STRIDE + i0 + 1];
            r0 += e0; r1 += e1;
            float v0 = V[sc * S_STRIDE + j0 + 0], v1 = V[sc * S_STRIDE + j0 + 1];
            float v2 = V[sc * S_STRIDE + j0 + 2], v3 = V[sc * S_STRIDE + j0 + 3];
            cacc[0] += e0 * v0; cacc[1] += e0 * v1;
            cacc[2] += e0 * v2; cacc[3] += e0 * v3;
            cacc[4] += e1 * v0; cacc[5] += e1 * v1;
            cacc[6] += e1 * v2; cacc[7] += e1 * v3;
        }
        int gh = b * 8 + p * 2 + h;
        float* c0 = &g_ctx[(gh * 32 + i0) * 32 + j0];
        atomicAdd(c0 + 0, cacc[0]); atomicAdd(c0 + 1, cacc[1]);
        atomicAdd(c0 + 2, cacc[2]); atomicAdd(c0 + 3, cacc[3]);
        atomicAdd(c0 + 32, cacc[4]); atomicAdd(c0 + 33, cacc[5]);
        atomicAdd(c0 + 34, cacc[6]); atomicAdd(c0 + 35, cacc[7]);
        if (j0 == 0) {
            atomicAdd(&g_rsum[gh * 32 + i0], r0);
            atomicAdd(&g_rsum[gh * 32 + i0 + 1], r1);
        }
    }
}

// ------------------------------------------------------------- k_M3
__global__ __launch_bounds__(256) void k_M3(const float* __restrict__ wo)
{
    __shared__ float sctx[256 * 33];
    __shared__ float sw[256];
    __shared__ float sinv[256];
    int b = blockIdx.x, ot = blockIdx.y, tid = threadIdx.x;
    for (int idx = tid; idx < 8192; idx += 256) {
        int row = idx >> 5, j = idx & 31;
        sctx[row * 33 + j] = g_ctx[b * 8192 + idx];
    }
    sinv[tid] = 0.17677669529663687f / g_rsum[b * 256 + tid];
    __syncthreads();
    int n = tid >> 5;
    for (int oo = 0; oo < 32; oo++) {
        int o = ot * 32 + oo;
        __syncthreads();
        sw[tid] = wo[o * 256 + tid];
        __syncthreads();
        float s = 0.f;
        #pragma unroll
        for (int j = 0; j < 32; j++) s += sw[n * 32 + j] * sctx[tid * 33 + j];
        float m = s * sinv[tid];
        __nv_bfloat16 h = __float2bfloat16(m);
        g_M3h[(size_t)(b * 256 + o) * 256 + tid] = h;
        g_M3l[(size_t)(b * 256 + o) * 256 + tid] =
            __float2bfloat16(m - __bfloat162float(h));
    }
}

// ------------------------------------------------------------- K3
__global__ void __launch_bounds__(256, 2) k3(const float* __restrict__ bo,
                                             float* __restrict__ outp)
{
    extern __shared__ char sm[];
    const int tid = threadIdx.x;
    const int b = blockIdx.z, y = blockIdx.y, s0 = blockIdx.x * 128;

    float acc[4][4][4];
    gemm128(sm, acc,
            g_M3h + (size_t)(b * 256 + y * 128) * 256,
            g_M3l + (size_t)(b * 256 + y * 128) * 256,
            g_qsTh + ((size_t)b * SS + s0) * 256,
            g_qsTl + ((size_t)b * SS + s0) * 256);

    float* S = (float*)sm;                       // [128 row][132 spatial]
    float* sbias = (float*)(sm + OFF_BIAS);
    acc_to_smem<false>(S, acc);
    if (tid < 128) sbias[tid] = bo[y * 128 + tid];
    __syncthreads();

    #pragma unroll 4
    for (int i2 = tid; i2 < 128 * 32; i2 += 256) {
        int rr = i2 >> 5, c4 = (i2 & 31) * 4;
        float4 v = *(float4*)(S + rr * S_STRIDE + c4);
        float bb2 = sbias[rr];
        v.x += bb2; v.y += bb2; v.z += bb2; v.w += bb2;
        *(float4*)(outp + (size_t)(b * 256 + y * 128 + rr) * SS + s0 + c4) = v;
    }
}

// ---------------------------------------------------------------------------
extern "C" void kernel_launch(void* const* d_in, const int* in_sizes, int n_in,
                              void* d_out, int out_size)
{
    const float* q  = (const float*)d_in[0];
    const float* wq = (const float*)d_in[1];
    const float* bq = (const float*)d_in[2];
    const float* wk = (const float*)d_in[3];
    const float* bk = (const float*)d_in[4];
    const float* wv = (const float*)d_in[5];
    const float* bv = (const float*)d_in[6];
    const float* wo = (const float*)d_in[7];
    const float* bo = (const float*)d_in[8];
    float* out = (float*)d_out;

    static int once = 0;
    if (!once) {
        cudaFuncSetAttribute(k1, cudaFuncAttributeMaxDynamicSharedMemorySize, SMEM_DYN);
        cudaFuncSetAttribute(k3, cudaFuncAttributeMaxDynamicSharedMemorySize, SMEM_DYN);
        once = 1;
    }

    k_prepw<<<768, 256>>>(wq, bq, wk, bk, wv, bv);
    k_prepq<<<dim3(SS / 64, 4, BB), 256>>>(q);
    k1<<<dim3(SS / 128, 6, BB), 256, SMEM_DYN>>>();
    k_M3<<<dim3(BB, 8), 256>>>(wo);
    k3<<<dim3(SS / 128, 2, BB), 256, SMEM_DYN>>>(bo, out);
}

// round 12
// speedup vs baseline: 3.4234x; 1.0238x over previous
#include <cuda_runtime.h>
#include <cuda_bf16.h>
#include <cstdint>

#define BB 8
#define SS 16384

// ------------------------------------------------------------- device scratch
__device__ __align__(16) __nv_bfloat16 g_qTh [BB * SS * 256];
__device__ __align__(16) __nv_bfloat16 g_qTl [BB * SS * 256];
__device__ __align__(16) __nv_bfloat16 g_qsTh[BB * SS * 256];
__device__ __align__(16) __nv_bfloat16 g_qsTl[BB * SS * 256];
__device__ __align__(16) __nv_bfloat16 g_W1h [768 * 256];
__device__ __align__(16) __nv_bfloat16 g_W1l [768 * 256];
__device__ float         g_bias1[768];
__device__ float         g_ctx [BB * 8 * 32 * 32];
__device__ float         g_rsum[BB * 256];
__device__ __align__(16) __nv_bfloat16 g_M3h [BB * 256 * 256];
__device__ __align__(16) __nv_bfloat16 g_M3l [BB * 256 * 256];

// ------------------------------------------------------------- smem layout
// Stage = A-pair tile (128 rows x [hi 64B | lo 64B], SW128 swizzle) + B-pair.
#define PAIR_B   16384               // 128*128
#define STAGE_B  32768               // A-pair + B-pair
#define NSTAGE   3
#define SMEM_DYN 98304               // 3 stages (epilogue reuse fits: 68096)
// Epilogue (reuses same smem): S fp32 [128][132] + bias[128]
#define S_STRIDE 132
#define OFF_BIAS 67584               // bytes (= 128*132*4)
// k_M3 dynamic smem: sctx [256][33] + swo [32][256]
#define M3_SMEM  66560

// ------------------------------------------------------------- PTX helpers
__device__ __forceinline__ uint32_t smem_u32(const void* p) {
    uint32_t a;
    asm("{ .reg .u64 t; cvta.to.shared.u64 t, %1; cvt.u32.u64 %0, t; }"
        : "=r"(a) : "l"(p));
    return a;
}
__device__ __forceinline__ void cpa16(uint32_t s, const void* g) {
    asm volatile("cp.async.cg.shared.global [%0], [%1], 16;" :: "r"(s), "l"(g));
}
__device__ __forceinline__ void cpa_commit() {
    asm volatile("cp.async.commit_group;" ::: "memory");
}
__device__ __forceinline__ void ldsm4(uint32_t* r, uint32_t addr) {
    asm volatile("ldmatrix.sync.aligned.m8n8.x4.shared.b16 {%0,%1,%2,%3}, [%4];"
                 : "=r"(r[0]), "=r"(r[1]), "=r"(r[2]), "=r"(r[3]) : "r"(addr));
}
__device__ __forceinline__ void mma16816(float* c, const uint32_t* a,
                                         const uint32_t* b) {
    asm volatile(
        "mma.sync.aligned.m16n8k16.row.col.f32.bf16.bf16.f32 "
        "{%0,%1,%2,%3}, {%4,%5,%6,%7}, {%8,%9}, {%0,%1,%2,%3};"
        : "+f"(c[0]), "+f"(c[1]), "+f"(c[2]), "+f"(c[3])
        : "r"(a[0]), "r"(a[1]), "r"(a[2]), "r"(a[3]), "r"(b[0]), "r"(b[1]));
}

// ------------------------------------------------------------- prep kernels
// Also zeroes ctx/rsum accumulators (folded launch).
__global__ void k_prepw(const float* __restrict__ wq, const float* __restrict__ bq,
                        const float* __restrict__ wk, const float* __restrict__ bk,
                        const float* __restrict__ wv, const float* __restrict__ bv)
{
    int r = blockIdx.x, k = threadIdx.x;
    int z = r * 256 + k;
    if (z < BB * 8 * 32 * 32) g_ctx[z] = 0.f;
    if (z < BB * 256)         g_rsum[z] = 0.f;

    const float *W, *Bp; int src;
    if (r < 256) { W = wq; Bp = bq; src = r; }
    else {
        int q2 = r - 256, p = q2 >> 7, lr = q2 & 127;
        int sub = lr >> 5, ch = lr & 31, head = 2 * p + (sub >> 1);
        W = (sub & 1) ? wv : wk;  Bp = (sub & 1) ? bv : bk;
        src = head * 32 + ch;
    }
    float v = W[src * 256 + k];
    __nv_bfloat16 h = __float2bfloat16(v);
    g_W1h[r * 256 + k] = h;
    g_W1l[r * 256 + k] = __float2bfloat16(v - __bfloat162float(h));
    if (k == 0) g_bias1[r] = Bp[src];
}

// transpose q [b][c][s] -> qT [b][s][c], hi/lo bf16. 64c x 64s tiles.
__global__ __launch_bounds__(256) void k_prepq(const float* __restrict__ q)
{
    __shared__ float tile[64 * 68];
    int tid = threadIdx.x;
    int s0 = blockIdx.x * 64, c0 = blockIdx.y * 64, b = blockIdx.z;
    #pragma unroll
    for (int it = 0; it < 4; it++) {
        int i = tid + it * 256;
        int r = i >> 4, c4 = (i & 15) * 4;
        float4 v = *(const float4*)(q + (size_t)(b * 256 + c0 + r) * SS + s0 + c4);
        *(float4*)(tile + r * 68 + c4) = v;
    }
    __syncthreads();
    #pragma unroll
    for (int it = 0; it < 8; it++) {
        int u = tid + it * 256;
        int sl = u >> 5, cp = u & 31;
        float a = tile[(cp * 2 + 0) * 68 + sl];
        float c = tile[(cp * 2 + 1) * 68 + sl];
        __nv_bfloat16 ha = __float2bfloat16(a), hc = __float2bfloat16(c);
        __nv_bfloat162 hp = __halves2bfloat162(ha, hc);
        __nv_bfloat162 lp = __halves2bfloat162(
            __float2bfloat16(a - __bfloat162float(ha)),
            __float2bfloat16(c - __bfloat162float(hc)));
        size_t idx = ((size_t)(b * SS + s0 + sl) * 256 + c0) / 2 + cp;
        ((uint32_t*)g_qTh)[idx] = *(uint32_t*)&hp;
        ((uint32_t*)g_qTl)[idx] = *(uint32_t*)&lp;
    }
}

// ------------------------------------------------------------- GEMM mainloop
// 128x128x256 per CTA; warp (wm,wn) owns 64x32; acc[mi][ni][4] fp32.
// Stage layout: A-pair rows: [Ah(k 0..31) | Al(k 0..31)], SW128-swizzled.
__device__ __forceinline__ void load_chunk(
    uint32_t sb, int kc, int tid,
    const __nv_bfloat16* Ah, const __nv_bfloat16* Al,
    const __nv_bfloat16* Bh, const __nv_bfloat16* Bl)
{
    const int c16 = tid & 7;
    const __nv_bfloat16* srcA = (c16 < 4 ? Ah : Al);
    const __nv_bfloat16* srcB = (c16 < 4 ? Bh : Bl);
    const int kb = kc * 32 + (c16 & 3) * 8;
    #pragma unroll
    for (int it = 0; it < 4; it++) {
        int row = (tid >> 3) + it * 32;
        uint32_t so = row * 128 + ((c16 ^ (row & 7)) << 4);
        cpa16(sb + so,          srcA + (size_t)row * 256 + kb);
        cpa16(sb + PAIR_B + so, srcB + (size_t)row * 256 + kb);
    }
}

__device__ __forceinline__ void gemm128(
    char* sm, float (&acc)[4][4][4],
    const __nv_bfloat16* Ah, const __nv_bfloat16* Al,
    const __nv_bfloat16* Bh, const __nv_bfloat16* Bl)
{
    const int tid = threadIdx.x, w = tid >> 5, l = tid & 31;
    const int wm = w >> 2, wn = w & 3;
    uint32_t smb = smem_u32(sm);

    #pragma unroll
    for (int mi = 0; mi < 4; mi++)
        #pragma unroll
        for (int ni = 0; ni < 4; ni++)
            #pragma unroll
            for (int r = 0; r < 4; r++) acc[mi][ni][r] = 0.f;

    // per-lane ldmatrix row bases (row&7 invariant under +16-row steps)
    const int arow = wm * 64 + (l & 7) + ((l >> 3) & 1) * 8;
    const uint32_t a_off = (uint32_t)arow * 128;
    const int arsw = arow & 7, la = l >> 4;
    const int brow = wn * 32 + (l & 7) + (l >> 4) * 8;
    const uint32_t b_off = PAIR_B + (uint32_t)brow * 128;
    const int brsw = brow & 7, lb = (l >> 3) & 1;

    load_chunk(smb, 0, tid, Ah, Al, Bh, Bl);
    cpa_commit();

    uint32_t st = smb, ld = smb + STAGE_B;
    #pragma unroll 1
    for (int c = 0; c < 8; c++) {
        if (c < 7) {
            load_chunk(ld, c + 1, tid, Ah, Al, Bh, Bl);
            cpa_commit();
            ld += STAGE_B; if (ld == smb + NSTAGE * STAGE_B) ld = smb;
            asm volatile("cp.async.wait_group 1;" ::: "memory");
        } else {
            asm volatile("cp.async.wait_group 0;" ::: "memory");
        }
        __syncthreads();
        #pragma unroll
        for (int ks = 0; ks < 2; ks++) {
            uint32_t bh[4][2], bl4[4][2], t4[4];
            #pragma unroll
            for (int half = 0; half < 2; half++) {
                uint32_t ba = st + b_off + half * 2048 +
                              (((ks * 2 + lb) ^ brsw) << 4);
                ldsm4(t4, ba);
                bh[2*half][0] = t4[0]; bh[2*half][1] = t4[1];
                bh[2*half+1][0] = t4[2]; bh[2*half+1][1] = t4[3];
                ldsm4(t4, ba ^ 64);
                bl4[2*half][0] = t4[0]; bl4[2*half][1] = t4[1];
                bl4[2*half+1][0] = t4[2]; bl4[2*half+1][1] = t4[3];
            }
            #pragma unroll
            for (int mi = 0; mi < 4; mi++) {
                uint32_t ah[4], al4[4];
                uint32_t aa = st + a_off + mi * 2048 +
                              (((ks * 2 + la) ^ arsw) << 4);
                ldsm4(ah, aa);
                ldsm4(al4, aa ^ 64);
                #pragma unroll
                for (int ni = 0; ni < 4; ni++) {
                    mma16816(acc[mi][ni], ah,  bh[ni]);
                    mma16816(acc[mi][ni], ah,  bl4[ni]);
                    mma16816(acc[mi][ni], al4, bh[ni]);
                }
            }
        }
        st += STAGE_B; if (st == smb + NSTAGE * STAGE_B) st = smb;
    }
    __syncthreads();   // protect stage smem before epilogue reuse
}

// store acc into S: transposed (S[spatial][channel]) if T, else natural.
template<bool T>
__device__ __forceinline__ void acc_to_smem(float* S, float (&acc)[4][4][4])
{
    const int tid = threadIdx.x, w = tid >> 5, l = tid & 31;
    const int wm = w >> 2, wn = w & 3;
    const int r0 = wm * 64 + (l >> 2), c0 = wn * 32 + (l & 3) * 2;
    #pragma unroll
    for (int mi = 0; mi < 4; mi++)
        #pragma unroll
        for (int ni = 0; ni < 4; ni++) {
            int r = r0 + mi * 16, cc = c0 + ni * 8;
            if (T) {
                S[cc * S_STRIDE + r]           = acc[mi][ni][0];
                S[(cc + 1) * S_STRIDE + r]     = acc[mi][ni][1];
                S[cc * S_STRIDE + r + 8]       = acc[mi][ni][2];
                S[(cc + 1) * S_STRIDE + r + 8] = acc[mi][ni][3];
            } else {
                S[r * S_STRIDE + cc]           = acc[mi][ni][0];
                S[r * S_STRIDE + cc + 1]       = acc[mi][ni][1];
                S[(r + 8) * S_STRIDE + cc]     = acc[mi][ni][2];
                S[(r + 8) * S_STRIDE + cc + 1] = acc[mi][ni][3];
            }
        }
}

// ------------------------------------------------------------- K1
__global__ void __launch_bounds__(256, 2) k1()
{
    extern __shared__ char sm[];
    const int tid = threadIdx.x;
    const int b = blockIdx.z, y = blockIdx.y, s0 = blockIdx.x * 128;

    float acc[4][4][4];
    gemm128(sm, acc,
            g_W1h + y * 128 * 256, g_W1l + y * 128 * 256,
            g_qTh + ((size_t)b * SS + s0) * 256,
            g_qTl + ((size_t)b * SS + s0) * 256);

    float* S = (float*)sm;                       // [128 spatial][132 channel]
    float* sbias = (float*)(sm + OFF_BIAS);
    acc_to_smem<true>(S, acc);
    if (tid < 128) sbias[tid] = g_bias1[y * 128 + tid];
    __syncthreads();

    if (y < 2) {
        // ---- q epilogue: softmax over d=32 per spatial, split hi/lo, write qsT
        const int sc = tid >> 1;
        #pragma unroll
        for (int g2 = 0; g2 < 2; g2++) {
            const int g = (tid & 1) * 2 + g2, gb = g * 32;
            float e[32], sum = 0.f;
            #pragma unroll
            for (int i = 0; i < 32; i++) {
                e[i] = __expf(S[sc * S_STRIDE + gb + i] + sbias[gb + i]);
                sum += e[i];
            }
            float inv = __fdividef(1.f, sum);
            __nv_bfloat16 oh[32], ol[32];
            #pragma unroll
            for (int i = 0; i < 32; i++) {
                float qv = e[i] * inv;
                __nv_bfloat16 h = __float2bfloat16(qv);
                oh[i] = h;
                ol[i] = __float2bfloat16(qv - __bfloat162float(h));
            }
            size_t go = ((size_t)b * SS + s0 + sc) * 256 + y * 128 + gb;
            #pragma unroll
            for (int v = 0; v < 4; v++) {
                *(uint4*)(g_qsTh + go + v * 8) = *(uint4*)(oh + v * 8);
                *(uint4*)(g_qsTl + go + v * 8) = *(uint4*)(ol + v * 8);
            }
        }
    } else {
        // ---- kv epilogue: in-place exp(k)+bias / v+bias, then ctx/rsum
        const int p = y - 2;
        {
            const int ch = tid & 127;
            const float bias = sbias[ch];
            const bool isk = ((ch >> 5) & 1) == 0;
            #pragma unroll 8
            for (int i = 0; i < 64; i++) {
                int sc = 2 * i + (tid >> 7);
                float v = S[sc * S_STRIDE + ch] + bias;
                S[sc * S_STRIDE + ch] = isk ? __expf(v) : v;
            }
        }
        __syncthreads();
        const int h = tid >> 7, i0 = ((tid >> 3) & 15) * 2, j0 = (tid & 7) * 4;
        float cacc[8] = {0,0,0,0,0,0,0,0};
        float r0 = 0.f, r1 = 0.f;
        const float* E = S + h * 64 + i0;
        const float* V = S + h * 64 + 32 + j0;
        #pragma unroll 4
        for (int sc = 0; sc < 128; sc++) {
            float2 e = *(const float2*)(E + sc * S_STRIDE);
            float4 v = *(const float4*)(V + sc * S_STRIDE);
            r0 += e.x; r1 += e.y;
            cacc[0] += e.x * v.x; cacc[1] += e.x * v.y;
            cacc[2] += e.x * v.z; cacc[3] += e.x * v.w;
            cacc[4] += e.y * v.x; cacc[5] += e.y * v.y;
            cacc[6] += e.y * v.z; cacc[7] += e.y * v.w;
        }
        int gh = b * 8 + p * 2 + h;
        float* c0 = &g_ctx[(gh * 32 + i0) * 32 + j0];
        atomicAdd(c0 + 0, cacc[0]); atomicAdd(c0 + 1, cacc[1]);
        atomicAdd(c0 + 2, cacc[2]); atomicAdd(c0 + 3, cacc[3]);
        atomicAdd(c0 + 32, cacc[4]); atomicAdd(c0 + 33, cacc[5]);
        atomicAdd(c0 + 34, cacc[6]); atomicAdd(c0 + 35, cacc[7]);
        if (j0 == 0) {
            atomicAdd(&g_rsum[gh * 32 + i0], r0);
            atomicAdd(&g_rsum[gh * 32 + i0 + 1], r1);
        }
    }
}

// ------------------------------------------------------------- k_M3
// One block per (batch, 32-row o-chunk). Preload ctx + wo rows, then a
// sync-free per-thread loop (wo reads are warp-uniform smem broadcasts).
__global__ __launch_bounds__(256) void k_M3(const float* __restrict__ wo)
{
    extern __shared__ float dsm[];
    float* sctx = dsm;               // [256][33] (pitch kills conflicts)
    float* swo  = dsm + 256 * 33;    // [32][256]
    const int b = blockIdx.x, ot = blockIdx.y, tid = threadIdx.x;

    for (int idx = tid; idx < 8192; idx += 256) {
        sctx[(idx >> 5) * 33 + (idx & 31)] = g_ctx[b * 8192 + idx];
        swo[idx] = wo[(size_t)(ot * 32) * 256 + idx];
    }
    const float inv = 0.17677669529663687f / g_rsum[b * 256 + tid];
    __syncthreads();

    float creg[32];
    #pragma unroll
    for (int j = 0; j < 32; j++) creg[j] = sctx[tid * 33 + j];
    const float* swn = swo + (tid >> 5) * 32;

    #pragma unroll 4
    for (int oo = 0; oo < 32; oo++) {
        float s = 0.f;
        #pragma unroll
        for (int j = 0; j < 32; j++) s += swn[oo * 256 + j] * creg[j];
        float m = s * inv;
        __nv_bfloat16 h = __float2bfloat16(m);
        size_t o = (size_t)(b * 256 + ot * 32 + oo) * 256 + tid;
        g_M3h[o] = h;
        g_M3l[o] = __float2bfloat16(m - __bfloat162float(h));
    }
}

// ------------------------------------------------------------- K3
__global__ void __launch_bounds__(256, 2) k3(const float* __restrict__ bo,
                                             float* __restrict__ outp)
{
    extern __shared__ char sm[];
    const int tid = threadIdx.x;
    const int b = blockIdx.z, y = blockIdx.y, s0 = blockIdx.x * 128;

    float acc[4][4][4];
    gemm128(sm, acc,
            g_M3h + (size_t)(b * 256 + y * 128) * 256,
            g_M3l + (size_t)(b * 256 + y * 128) * 256,
            g_qsTh + ((size_t)b * SS + s0) * 256,
            g_qsTl + ((size_t)b * SS + s0) * 256);

    float* S = (float*)sm;                       // [128 row][132 spatial]
    float* sbias = (float*)(sm + OFF_BIAS);
    acc_to_smem<false>(S, acc);
    if (tid < 128) sbias[tid] = bo[y * 128 + tid];
    __syncthreads();

    #pragma unroll 4
    for (int i2 = tid; i2 < 128 * 32; i2 += 256) {
        int rr = i2 >> 5, c4 = (i2 & 31) * 4;
        float4 v = *(float4*)(S + rr * S_STRIDE + c4);
        float bb2 = sbias[rr];
        v.x += bb2; v.y += bb2; v.z += bb2; v.w += bb2;
        *(float4*)(outp + (size_t)(b * 256 + y * 128 + rr) * SS + s0 + c4) = v;
    }
}

// ---------------------------------------------------------------------------
extern "C" void kernel_launch(void* const* d_in, const int* in_sizes, int n_in,
                              void* d_out, int out_size)
{
    const float* q  = (const float*)d_in[0];
    const float* wq = (const float*)d_in[1];
    const float* bq = (const float*)d_in[2];
    const float* wk = (const float*)d_in[3];
    const float* bk = (const float*)d_in[4];
    const float* wv = (const float*)d_in[5];
    const float* bv = (const float*)d_in[6];
    const float* wo = (const float*)d_in[7];
    const float* bo = (const float*)d_in[8];
    float* out = (float*)d_out;

    static int once = 0;
    if (!once) {
        cudaFuncSetAttribute(k1, cudaFuncAttributeMaxDynamicSharedMemorySize, SMEM_DYN);
        cudaFuncSetAttribute(k3, cudaFuncAttributeMaxDynamicSharedMemorySize, SMEM_DYN);
        cudaFuncSetAttribute(k_M3, cudaFuncAttributeMaxDynamicSharedMemorySize, M3_SMEM);
        once = 1;
    }

    k_prepw<<<768, 256>>>(wq, bq, wk, bk, wv, bv);
    k_prepq<<<dim3(SS / 64, 4, BB), 256>>>(q);
    k1<<<dim3(SS / 128, 6, BB), 256, SMEM_DYN>>>();
    k_M3<<<dim3(BB, 8), 256, M3_SMEM>>>(wo);
    k3<<<dim3(SS / 128, 2, BB), 256, SMEM_DYN>>>(bo, out);
}